// round 8
// baseline (speedup 1.0000x reference)
#include <cuda_runtime.h>
#include <cuda_fp16.h>
#include <math.h>
#include <stdint.h>

// ---------------- problem constants ----------------
#define BATCH   2
#define SEQL    1024
#define DMODEL  1024
#define DINNER  2048
#define DSTATE  16
#define DCONV   4
#define DTRANK  64
#define NTOK    (BATCH * SEQL)          // 2048
#define XDBL_LD 128                     // padded (dt 0..63 | B 64..79 | C 80..95 | pad)
#define NCHUNK  8
#define CLEN    (SEQL / NCHUNK)         // 128

// ---------------- PTX helpers (portable: sm_80-era features only) ----------------
__device__ __forceinline__ uint32_t smem_to_u32(const void* p) {
    uint32_t a;
    asm("{ .reg .u64 t; cvta.to.shared.u64 t, %1; cvt.u32.u64 %0, t; }" : "=r"(a) : "l"(p));
    return a;
}
__device__ __forceinline__ void cpasync16(uint32_t s, const void* g) {
    asm volatile("cp.async.cg.shared.global [%0], [%1], 16;" :: "r"(s), "l"(g));
}
#define CP_COMMIT()  asm volatile("cp.async.commit_group;" ::: "memory")
#define CP_WAIT0()   asm volatile("cp.async.wait_group 0;" ::: "memory")
#define CP_WAIT1()   asm volatile("cp.async.wait_group 1;" ::: "memory")
#define LDSM4(r, addr) \
    asm volatile("ldmatrix.sync.aligned.m8n8.x4.shared.b16 {%0,%1,%2,%3}, [%4];" \
        : "=r"((r)[0]), "=r"((r)[1]), "=r"((r)[2]), "=r"((r)[3]) : "r"(addr))

__device__ __forceinline__ void mma16816(float* d, const uint32_t* a, const uint32_t* b) {
    asm volatile(
        "mma.sync.aligned.m16n8k16.row.col.f32.f16.f16.f32 "
        "{%0,%1,%2,%3}, {%4,%5,%6,%7}, {%8,%9}, {%0,%1,%2,%3};"
        : "+f"(d[0]), "+f"(d[1]), "+f"(d[2]), "+f"(d[3])
        : "r"(a[0]), "r"(a[1]), "r"(a[2]), "r"(a[3]), "r"(b[0]), "r"(b[1]));
}

// swizzled byte offset of 16B chunk c (0..7) in row r (row = 128 bytes = 8 chunks)
// ldmatrix 8-row tiles hit 8 distinct 16B banks: c ^= r & 7
__device__ __forceinline__ uint32_t sw_off(int r, int c) {
    return (uint32_t)(r * 128 + ((c ^ (r & 7)) << 4));
}

// ---------------- scratch (device globals) ----------------
__device__ float g_xz[(size_t)NTOK * 2 * DINNER];     // u_raw (z half unused)
__device__ float g_zs[(size_t)NTOK * DINNER];
__device__ float g_xdbl[(size_t)NTOK * XDBL_LD];
__device__ float g_delta[(size_t)NTOK * DINNER];
__device__ float g_osplit[(size_t)4 * NTOK * DMODEL]; // split-K buffers for out GEMM
// chunked-scan state
__device__ float g_hend[(size_t)BATCH * DINNER * DSTATE * NCHUNK];
__device__ float g_h0[(size_t)BATCH * DINNER * DSTATE * NCHUNK];
__device__ float g_sumd[(size_t)BATCH * DINNER * NCHUNK];

// A-side: fp16 two-term split (hi + lo ~ 22 mantissa bits)
__device__ __half g_xh[(size_t)NTOK * DMODEL],   g_xl[(size_t)NTOK * DMODEL];
__device__ __half g_uh[(size_t)NTOK * DINNER],   g_ul[(size_t)NTOK * DINNER];
__device__ __half g_yh[(size_t)NTOK * DINNER],   g_yl[(size_t)NTOK * DINNER];
__device__ __half g_dth[(size_t)NTOK * DTRANK],  g_dtl[(size_t)NTOK * DTRANK];
// B-side: transposed single fp16 weights: [N][K] row-major (K contiguous)
__device__ __half g_wint[(size_t)2 * DINNER * DMODEL];
__device__ __half g_wxt[(size_t)XDBL_LD * DINNER];
__device__ __half g_wdtt[(size_t)DINNER * DTRANK];
__device__ __half g_wot[(size_t)DMODEL * DINNER];

// ---------------- mma.sync fp16 2-pass GEMM, K-tile 64, 2-stage pipeline ----------------
// C[M,N] = (Ah+Al)[M,K] @ B[K,N], B given transposed [N][K], fp32 accum.
// EPI 0: store (+zstride per blockIdx.z), 1: softplus(acc+bias), 2: atomicAdd,
// EPI 3: store u-half raw; z-half -> silu to g_zs
#define STAGE_B 49152
#define MG_SMEM (2 * STAGE_B)
template <int EPI>
__global__ __launch_bounds__(256, 2) void mma_gemm(
    const __half* __restrict__ Ah, const __half* __restrict__ Al, int lda,
    const __half* __restrict__ B, int ldb,
    float* __restrict__ C, int ldc, int K, int KS, const float* __restrict__ bias,
    int zstride)
{
    extern __shared__ char smem[];
    uint32_t sb = smem_to_u32(smem);
    const int tid = threadIdx.x, lane = tid & 31, wid = tid >> 5;
    const int wm = wid & 3, wn = wid >> 2;          // warp tile: rows wm*32, cols wn*64
    const int row0 = blockIdx.y * 128, col0 = blockIdx.x * 128;
    const int kper = K / KS;
    const int kbeg = blockIdx.z * kper;
    const int kn = kper >> 6;                        // 64-wide k tiles

    float acc[2][8][4];
#pragma unroll
    for (int i = 0; i < 2; i++)
#pragma unroll
        for (int j = 0; j < 8; j++)
#pragma unroll
            for (int r = 0; r < 4; r++) acc[i][j][r] = 0.f;

    // stage layout: Ah 0..16K, Al 16K..32K, B 32K..48K   (128 rows x 128B each)
    auto load_stage = [&](int s, int k0) {
        uint32_t base = sb + s * STAGE_B;
#pragma unroll
        for (int j = 0; j < 4; j++) {
            int idx = tid + j * 256;                 // 0..1023
            int r = idx >> 3, c = idx & 7;
            uint32_t so = sw_off(r, c);
            size_t ao = (size_t)(row0 + r) * lda + k0 + c * 8;
            size_t bo = (size_t)(col0 + r) * ldb + k0 + c * 8;
            cpasync16(base + so,           Ah + ao);
            cpasync16(base + 16384 + so,   Al + ao);
            cpasync16(base + 32768 + so,   B + bo);
        }
        CP_COMMIT();
    };

    load_stage(0, kbeg);

    const int a_row = wm * 32 + ((lane >> 3) & 1) * 8 + (lane & 7);   // + mi*16
    const int b_row = wn * 64 + (lane >> 4) * 8 + (lane & 7);         // + j*16

    for (int it = 0; it < kn; it++) {
        if (it + 1 < kn) {
            load_stage((it + 1) & 1, kbeg + (it + 1) * 64);
            CP_WAIT1();
        } else {
            CP_WAIT0();
        }
        __syncthreads();
        uint32_t base = sb + (it & 1) * STAGE_B;
#pragma unroll
        for (int kk = 0; kk < 4; kk++) {
            uint32_t ah[2][4], al[2][4], bb[8][2];
#pragma unroll
            for (int mi = 0; mi < 2; mi++) {
                int r = a_row + mi * 16;
                int c = kk * 2 + (lane >> 4);
                uint32_t so = sw_off(r, c);
                LDSM4(ah[mi], base + so);
                LDSM4(al[mi], base + 16384 + so);
            }
#pragma unroll
            for (int j = 0; j < 4; j++) {
                int r = b_row + j * 16;
                int c = kk * 2 + ((lane >> 3) & 1);
                uint32_t so = sw_off(r, c);
                uint32_t t[4];
                LDSM4(t, base + 32768 + so);
                bb[2 * j][0] = t[0]; bb[2 * j][1] = t[1];
                bb[2 * j + 1][0] = t[2]; bb[2 * j + 1][1] = t[3];
            }
#pragma unroll
            for (int mi = 0; mi < 2; mi++)
#pragma unroll
                for (int nj = 0; nj < 8; nj++) {
                    mma16816(acc[mi][nj], ah[mi], bb[nj]);
                    mma16816(acc[mi][nj], al[mi], bb[nj]);
                }
        }
        __syncthreads();   // protect stage (it+2)&1 == it&1 from next prefetch
    }

    if (EPI == 0) C += (size_t)blockIdx.z * zstride;

#pragma unroll
    for (int mi = 0; mi < 2; mi++) {
        int row = row0 + wm * 32 + mi * 16 + (lane >> 2);
#pragma unroll
        for (int nj = 0; nj < 8; nj++) {
            int col = col0 + wn * 64 + nj * 8 + (lane & 3) * 2;
            float* a = acc[mi][nj];
            if (EPI == 0) {
                *(float2*)&C[(size_t)row * ldc + col]       = make_float2(a[0], a[1]);
                *(float2*)&C[(size_t)(row + 8) * ldc + col] = make_float2(a[2], a[3]);
            } else if (EPI == 1) {
                float b0 = bias[col], b1 = bias[col + 1];
                float v0 = a[0] + b0, v1 = a[1] + b1, v2 = a[2] + b0, v3 = a[3] + b1;
                v0 = (v0 > 20.f) ? v0 : log1pf(expf(v0));
                v1 = (v1 > 20.f) ? v1 : log1pf(expf(v1));
                v2 = (v2 > 20.f) ? v2 : log1pf(expf(v2));
                v3 = (v3 > 20.f) ? v3 : log1pf(expf(v3));
                *(float2*)&C[(size_t)row * ldc + col]       = make_float2(v0, v1);
                *(float2*)&C[(size_t)(row + 8) * ldc + col] = make_float2(v2, v3);
            } else if (EPI == 2) {
                atomicAdd(&C[(size_t)row * ldc + col],           a[0]);
                atomicAdd(&C[(size_t)row * ldc + col + 1],       a[1]);
                atomicAdd(&C[(size_t)(row + 8) * ldc + col],     a[2]);
                atomicAdd(&C[(size_t)(row + 8) * ldc + col + 1], a[3]);
            } else {  // EPI == 3: xz epilogue. cols < DINNER raw; cols >= DINNER -> silu -> g_zs
                if (col < DINNER) {
                    *(float2*)&C[(size_t)row * ldc + col]       = make_float2(a[0], a[1]);
                    *(float2*)&C[(size_t)(row + 8) * ldc + col] = make_float2(a[2], a[3]);
                } else {
                    int zc = col - DINNER;
                    float s0 = a[0] / (1.f + __expf(-a[0]));
                    float s1 = a[1] / (1.f + __expf(-a[1]));
                    float s2 = a[2] / (1.f + __expf(-a[2]));
                    float s3 = a[3] / (1.f + __expf(-a[3]));
                    *(float2*)&g_zs[(size_t)row * DINNER + zc]       = make_float2(s0, s1);
                    *(float2*)&g_zs[(size_t)(row + 8) * DINNER + zc] = make_float2(s2, s3);
                }
            }
        }
    }
}

// ---------------- reduce 4 split-K buffers into out ----------------
__global__ void reduce4(const float* __restrict__ src, float* __restrict__ dst, int n4) {
    int i = blockIdx.x * blockDim.x + threadIdx.x;
    if (i >= n4) return;
    const float4* s = (const float4*)src;
    float4 a = s[i], b = s[i + n4], c = s[i + 2 * n4], d = s[i + 3 * n4];
    float4 r = make_float4(a.x + b.x + c.x + d.x, a.y + b.y + c.y + d.y,
                           a.z + b.z + c.z + d.z, a.w + b.w + c.w + d.w);
    ((float4*)dst)[i] = r;
}

// ---------------- elementwise split (fp32 -> fp16 hi/lo) ----------------
__global__ void cvt_split(const float* __restrict__ src,
                          __half* __restrict__ h, __half* __restrict__ l, int n)
{
    int i = blockIdx.x * blockDim.x + threadIdx.x;
    if (i >= n) return;
    float v = src[i];
    __half hi = __float2half_rn(v);
    h[i] = hi;
    l[i] = __float2half_rn(v - __half2float(hi));
}

// dt_lo slice of padded xdbl -> split arrays [2048][64]
__global__ void cvt_dt()
{
    int i = blockIdx.x * blockDim.x + threadIdx.x;   // < NTOK*64
    int t = i >> 6, c = i & 63;
    float v = g_xdbl[(size_t)t * XDBL_LD + c];
    __half hi = __float2half_rn(v);
    g_dth[i] = hi;
    g_dtl[i] = __float2half_rn(v - __half2float(hi));
}

// ---------------- transpose + convert:  W[K][N] -> T[Npad][K] (fp16, pad zero) ----------------
__global__ void transpose_cvt(const float* __restrict__ W, int K, int N,
                              __half* __restrict__ T)
{
    __shared__ float t[32][33];
    int bx = blockIdx.x, by = blockIdx.y;
    int tx = threadIdx.x, ty0 = threadIdx.y;
#pragma unroll
    for (int s = 0; s < 4; s++) {
        int ty = ty0 + s * 8;
        int col = bx * 32 + tx;          // n
        int row = by * 32 + ty;          // k
        t[ty][tx] = (col < N) ? W[(size_t)row * N + col] : 0.f;
    }
    __syncthreads();
#pragma unroll
    for (int s = 0; s < 4; s++) {
        int ty = ty0 + s * 8;
        int n = bx * 32 + ty;
        int k = by * 32 + tx;
        T[(size_t)n * K + k] = __float2half_rn(t[tx][ty]);
    }
}

// ---------------- zero fill ----------------
__global__ void zero_kernel(float* __restrict__ p, int n) {
    int i = blockIdx.x * blockDim.x + threadIdx.x;
    if (i < n) p[i] = 0.f;
}

// ---------------- conv + SiLU -> fp16 split of u (no fp32 u array) ----------------
__global__ void conv_silu(const float* __restrict__ ck, const float* __restrict__ cb)
{
    int idx = blockIdx.x * blockDim.x + threadIdx.x;
    if (idx >= NTOK * DINNER) return;
    int d  = idx & (DINNER - 1);
    int bt = idx >> 11;
    int t  = bt & (SEQL - 1);

    float acc = cb[d];
#pragma unroll
    for (int w = 0; w < DCONV; w++) {
        int tt = t - (DCONV - 1) + w;
        if (tt >= 0)
            acc = fmaf(ck[w * DINNER + d],
                       g_xz[(size_t)(bt - (DCONV - 1) + w) * (2 * DINNER) + d], acc);
    }
    float u = acc / (1.f + __expf(-acc));
    __half hi = __float2half_rn(u);
    g_uh[idx] = hi;
    g_ul[idx] = __float2half_rn(u - __half2float(hi));
}

// ---------------- chunked scan: phase 1 (chunk end-states, h0=0) ----------------
__global__ __launch_bounds__(256) void scan_phase1(const float* __restrict__ A_log)
{
    int tid = threadIdx.x;
    int ch = blockIdx.x * 16 + (tid >> 4);   // 0..4095
    int n = tid & 15;
    int c = blockIdx.y;
    int b = ch >> 11;
    int d = ch & (DINNER - 1);

    float a = -expf(A_log[d * DSTATE + n]);
    float h = 0.f, sd = 0.f;

    const float*  dptr = g_delta + (size_t)b * SEQL * DINNER + d + (size_t)c * CLEN * DINNER;
    const __half* uhp  = g_uh    + (size_t)b * SEQL * DINNER + d + (size_t)c * CLEN * DINNER;
    const __half* ulp  = g_ul    + (size_t)b * SEQL * DINNER + d + (size_t)c * CLEN * DINNER;
    const float*  xd   = g_xdbl  + (size_t)b * SEQL * XDBL_LD + (size_t)c * CLEN * XDBL_LD;

    for (int t = 0; t < CLEN; t++) {
        float delta = dptr[(size_t)t * DINNER];
        float uv    = __half2float(uhp[(size_t)t * DINNER]) + __half2float(ulp[(size_t)t * DINNER]);
        float Bn    = xd[t * XDBL_LD + DTRANK + n];
        h = __expf(delta * a) * h + delta * uv * Bn;
        sd += delta;
    }
    size_t idx = ((size_t)(b * DINNER + d) * DSTATE + n);
    g_hend[idx * NCHUNK + c] = h;
    if (n == 0) g_sumd[(size_t)(b * DINNER + d) * NCHUNK + c] = sd;
}

// ---------------- chunked scan: combine (sequential over 8 chunks) ----------------
__global__ void scan_combine(const float* __restrict__ A_log)
{
    int i = blockIdx.x * blockDim.x + threadIdx.x;     // < BATCH*DINNER*DSTATE
    if (i >= BATCH * DINNER * DSTATE) return;
    int n = i & 15;
    int d = (i >> 4) & (DINNER - 1);
    int bd = i >> 4;                                    // b*DINNER + d

    float a = -expf(A_log[d * DSTATE + n]);
    float H = 0.f;
#pragma unroll
    for (int c = 0; c < NCHUNK; c++) {
        g_h0[(size_t)i * NCHUNK + c] = H;
        float S = g_sumd[(size_t)bd * NCHUNK + c];
        H = __expf(a * S) * H + g_hend[(size_t)i * NCHUNK + c];
    }
}

// ---------------- chunked scan: phase 2 (y with true h0) ----------------
__global__ __launch_bounds__(256) void scan_phase2(
    const float* __restrict__ A_log, const float* __restrict__ Dp)
{
    int tid = threadIdx.x;
    int ch = blockIdx.x * 16 + (tid >> 4);
    int n = tid & 15;
    int c = blockIdx.y;
    int b = ch >> 11;
    int d = ch & (DINNER - 1);

    float a = -expf(A_log[d * DSTATE + n]);
    float Dd = Dp[d];
    float h = g_h0[((size_t)(b * DINNER + d) * DSTATE + n) * NCHUNK + c];

    const float*  dptr = g_delta + (size_t)b * SEQL * DINNER + d + (size_t)c * CLEN * DINNER;
    const __half* uhp  = g_uh    + (size_t)b * SEQL * DINNER + d + (size_t)c * CLEN * DINNER;
    const __half* ulp  = g_ul    + (size_t)b * SEQL * DINNER + d + (size_t)c * CLEN * DINNER;
    const float*  zptr = g_zs    + (size_t)b * SEQL * DINNER + d + (size_t)c * CLEN * DINNER;
    __half* yh = g_yh + (size_t)b * SEQL * DINNER + d + (size_t)c * CLEN * DINNER;
    __half* yl = g_yl + (size_t)b * SEQL * DINNER + d + (size_t)c * CLEN * DINNER;
    const float* xd = g_xdbl + (size_t)b * SEQL * XDBL_LD + (size_t)c * CLEN * XDBL_LD;

    for (int t = 0; t < CLEN; t++) {
        float delta = dptr[(size_t)t * DINNER];
        float uv    = __half2float(uhp[(size_t)t * DINNER]) + __half2float(ulp[(size_t)t * DINNER]);
        float Bn    = xd[t * XDBL_LD + DTRANK + n];
        float Cn    = xd[t * XDBL_LD + DTRANK + DSTATE + n];

        h = __expf(delta * a) * h + delta * uv * Bn;

        float p = h * Cn;
        p += __shfl_xor_sync(0xffffffffu, p, 8);
        p += __shfl_xor_sync(0xffffffffu, p, 4);
        p += __shfl_xor_sync(0xffffffffu, p, 2);
        p += __shfl_xor_sync(0xffffffffu, p, 1);

        if (n == 0) {
            float v = (p + uv * Dd) * zptr[(size_t)t * DINNER];
            __half hi = __float2half_rn(v);
            yh[(size_t)t * DINNER] = hi;
            yl[(size_t)t * DINNER] = __float2half_rn(v - __half2float(hi));
        }
    }
}

// ---------------- launch ----------------
extern "C" void kernel_launch(void* const* d_in, const int* in_sizes, int n_in,
                              void* d_out, int out_size)
{
    (void)in_sizes; (void)n_in; (void)out_size;
    const float* x     = (const float*)d_in[0];
    const float* W_in  = (const float*)d_in[1];
    const float* ck    = (const float*)d_in[2];
    const float* cb    = (const float*)d_in[3];
    const float* W_x   = (const float*)d_in[4];
    const float* W_dt  = (const float*)d_in[5];
    const float* b_dt  = (const float*)d_in[6];
    const float* W_out = (const float*)d_in[7];
    const float* A_log = (const float*)d_in[8];
    const float* Dp    = (const float*)d_in[9];
    float* out = (float*)d_out;

    cudaFuncSetAttribute(mma_gemm<0>, cudaFuncAttributeMaxDynamicSharedMemorySize, MG_SMEM);
    cudaFuncSetAttribute(mma_gemm<1>, cudaFuncAttributeMaxDynamicSharedMemorySize, MG_SMEM);
    cudaFuncSetAttribute(mma_gemm<2>, cudaFuncAttributeMaxDynamicSharedMemorySize, MG_SMEM);
    cudaFuncSetAttribute(mma_gemm<3>, cudaFuncAttributeMaxDynamicSharedMemorySize, MG_SMEM);

    float *p_xz, *p_xdbl, *p_delta, *p_osplit;
    cudaGetSymbolAddress((void**)&p_xz,    g_xz);
    cudaGetSymbolAddress((void**)&p_xdbl,  g_xdbl);
    cudaGetSymbolAddress((void**)&p_delta, g_delta);
    cudaGetSymbolAddress((void**)&p_osplit, g_osplit);
    __half *xh, *xl, *uh, *ul, *yh, *yl, *dth, *dtl;
    __half *wint, *wxt, *wdtt, *wot;
    cudaGetSymbolAddress((void**)&xh, g_xh);     cudaGetSymbolAddress((void**)&xl, g_xl);
    cudaGetSymbolAddress((void**)&uh, g_uh);     cudaGetSymbolAddress((void**)&ul, g_ul);
    cudaGetSymbolAddress((void**)&yh, g_yh);     cudaGetSymbolAddress((void**)&yl, g_yl);
    cudaGetSymbolAddress((void**)&dth, g_dth);   cudaGetSymbolAddress((void**)&dtl, g_dtl);
    cudaGetSymbolAddress((void**)&wint, g_wint);
    cudaGetSymbolAddress((void**)&wxt, g_wxt);
    cudaGetSymbolAddress((void**)&wdtt, g_wdtt);
    cudaGetSymbolAddress((void**)&wot, g_wot);

    // launch #1..#3: prep
    cvt_split<<<(NTOK * DMODEL + 255) / 256, 256>>>(x, xh, xl, NTOK * DMODEL);
    transpose_cvt<<<dim3(2 * DINNER / 32, DMODEL / 32), dim3(32, 8)>>>(W_in, DMODEL, 2 * DINNER, wint);
    transpose_cvt<<<dim3(DMODEL / 32, DINNER / 32), dim3(32, 8)>>>(W_out, DINNER, DMODEL, wot);

    // launch #4: xz = x @ W_in : M=2048, N=4096, K=1024; z half -> silu -> g_zs
    mma_gemm<3><<<dim3(32, 16, 1), 256, MG_SMEM>>>(
        xh, xl, DMODEL, wint, DMODEL, p_xz, 2 * DINNER, DMODEL, 1, nullptr, 0);

    // conv + silu -> u fp16 splits
    conv_silu<<<(NTOK * DINNER) / 256, 256>>>(ck, cb);

    // x_dbl = u @ W_x : M=2048, N=128(pad of 96), K=2048, split-K=8 atomics
    zero_kernel<<<(NTOK * XDBL_LD) / 256, 256>>>(p_xdbl, NTOK * XDBL_LD);
    transpose_cvt<<<dim3(XDBL_LD / 32, DINNER / 32), dim3(32, 8)>>>(W_x, DINNER, DTRANK + 2 * DSTATE, wxt);
    mma_gemm<2><<<dim3(1, 16, 8), 256, MG_SMEM>>>(
        uh, ul, DINNER, wxt, DINNER, p_xdbl, XDBL_LD, DINNER, 8, nullptr, 0);

    // delta = softplus(dt_lo @ W_dt + b_dt) : M=2048, N=2048, K=64 (single k-tile)
    cvt_dt<<<(NTOK * DTRANK) / 256, 256>>>();
    transpose_cvt<<<dim3(DINNER / 32, DTRANK / 32), dim3(32, 8)>>>(W_dt, DTRANK, DINNER, wdtt);
    mma_gemm<1><<<dim3(16, 16, 1), 256, MG_SMEM>>>(
        dth, dtl, DTRANK, wdtt, DTRANK, p_delta, DINNER, DTRANK, 1, b_dt, 0);

    // chunked selective scan
    scan_phase1<<<dim3((BATCH * DINNER) / 16, NCHUNK), 256>>>(A_log);
    scan_combine<<<(BATCH * DINNER * DSTATE) / 256, 256>>>(A_log);
    scan_phase2<<<dim3((BATCH * DINNER) / 16, NCHUNK), 256>>>(A_log, Dp);

    // out = y @ W_out : M=2048, N=1024, K=2048, split-K=4 -> buffers -> reduce
    mma_gemm<0><<<dim3(8, 16, 4), 256, MG_SMEM>>>(
        yh, yl, DINNER, wot, DINNER, p_osplit, DMODEL, DINNER, 4, nullptr, NTOK * DMODEL);
    reduce4<<<(NTOK * DMODEL / 4 + 255) / 256, 256>>>(p_osplit, out, NTOK * DMODEL / 4);
}

// round 9
// speedup vs baseline: 1.1718x; 1.1718x over previous
#include <cuda_runtime.h>
#include <cuda_fp16.h>
#include <math.h>
#include <stdint.h>

// ---------------- problem constants ----------------
#define BATCH   2
#define SEQL    1024
#define DMODEL  1024
#define DINNER  2048
#define DSTATE  16
#define DCONV   4
#define DTRANK  64
#define NTOK    (BATCH * SEQL)          // 2048
#define XDBL_LD 128                     // padded (dt 0..63 | B 64..79 | C 80..95 | pad)
#define NCHUNK  8
#define CLEN    (SEQL / NCHUNK)         // 128

// ---------------- PTX helpers (portable: sm_80-era features only) ----------------
__device__ __forceinline__ uint32_t smem_to_u32(const void* p) {
    uint32_t a;
    asm("{ .reg .u64 t; cvta.to.shared.u64 t, %1; cvt.u32.u64 %0, t; }" : "=r"(a) : "l"(p));
    return a;
}
__device__ __forceinline__ void cpasync16(uint32_t s, const void* g) {
    asm volatile("cp.async.cg.shared.global [%0], [%1], 16;" :: "r"(s), "l"(g));
}
#define CP_COMMIT()  asm volatile("cp.async.commit_group;" ::: "memory")
#define CP_WAIT0()   asm volatile("cp.async.wait_group 0;" ::: "memory")
#define CP_WAIT1()   asm volatile("cp.async.wait_group 1;" ::: "memory")
#define LDSM4(r, addr) \
    asm volatile("ldmatrix.sync.aligned.m8n8.x4.shared.b16 {%0,%1,%2,%3}, [%4];" \
        : "=r"((r)[0]), "=r"((r)[1]), "=r"((r)[2]), "=r"((r)[3]) : "r"(addr))

__device__ __forceinline__ void mma16816(float* d, const uint32_t* a, const uint32_t* b) {
    asm volatile(
        "mma.sync.aligned.m16n8k16.row.col.f32.f16.f16.f32 "
        "{%0,%1,%2,%3}, {%4,%5,%6,%7}, {%8,%9}, {%0,%1,%2,%3};"
        : "+f"(d[0]), "+f"(d[1]), "+f"(d[2]), "+f"(d[3])
        : "r"(a[0]), "r"(a[1]), "r"(a[2]), "r"(a[3]), "r"(b[0]), "r"(b[1]));
}

// swizzled byte offset of 16B chunk c (0..7) in row r (row = 128 bytes = 8 chunks)
__device__ __forceinline__ uint32_t sw_off(int r, int c) {
    return (uint32_t)(r * 128 + ((c ^ (r & 7)) << 4));
}

// ---------------- scratch (device globals) ----------------
__device__ float g_xz[(size_t)NTOK * 2 * DINNER];     // u_raw (z half unused)
__device__ float g_u[(size_t)NTOK * DINNER];          // fp32 u for the scan
__device__ float g_zs[(size_t)NTOK * DINNER];
__device__ float g_xdbl[(size_t)NTOK * XDBL_LD];
__device__ float g_delta[(size_t)NTOK * DINNER];
__device__ float g_osplit[(size_t)4 * NTOK * DMODEL]; // split-K buffers for out GEMM
// chunked-scan state
__device__ float g_hend[(size_t)BATCH * DINNER * DSTATE * NCHUNK];
__device__ float g_h0[(size_t)BATCH * DINNER * DSTATE * NCHUNK];
__device__ float g_sumd[(size_t)BATCH * DINNER * NCHUNK];

// A-side: fp16 two-term split (hi + lo ~ 22 mantissa bits)
__device__ __half g_xh[(size_t)NTOK * DMODEL],   g_xl[(size_t)NTOK * DMODEL];
__device__ __half g_uh[(size_t)NTOK * DINNER],   g_ul[(size_t)NTOK * DINNER];
__device__ __half g_yh[(size_t)NTOK * DINNER],   g_yl[(size_t)NTOK * DINNER];
__device__ __half g_dth[(size_t)NTOK * DTRANK],  g_dtl[(size_t)NTOK * DTRANK];
// B-side: transposed single fp16 weights: [N][K] row-major (K contiguous)
__device__ __half g_wint[(size_t)2 * DINNER * DMODEL];
__device__ __half g_wxt[(size_t)XDBL_LD * DINNER];
__device__ __half g_wdtt[(size_t)DINNER * DTRANK];
__device__ __half g_wot[(size_t)DMODEL * DINNER];

// ---------------- mma.sync fp16 2-pass GEMM, K-tile 64, 2-stage pipeline ----------------
// C[M,N] = (Ah+Al)[M,K] @ B[K,N], B given transposed [N][K], fp32 accum.
// EPI 0: store (+zstride per blockIdx.z), 1: softplus(acc+bias), 2: atomicAdd,
// EPI 3: store u-half raw; z-half -> silu to g_zs
#define STAGE_B 49152
#define MG_SMEM (2 * STAGE_B)
template <int EPI>
__global__ __launch_bounds__(256, 2) void mma_gemm(
    const __half* __restrict__ Ah, const __half* __restrict__ Al, int lda,
    const __half* __restrict__ B, int ldb,
    float* __restrict__ C, int ldc, int K, int KS, const float* __restrict__ bias,
    int zstride)
{
    extern __shared__ char smem[];
    uint32_t sb = smem_to_u32(smem);
    const int tid = threadIdx.x, lane = tid & 31, wid = tid >> 5;
    const int wm = wid & 3, wn = wid >> 2;          // warp tile: rows wm*32, cols wn*64
    const int row0 = blockIdx.y * 128, col0 = blockIdx.x * 128;
    const int kper = K / KS;
    const int kbeg = blockIdx.z * kper;
    const int kn = kper >> 6;                        // 64-wide k tiles

    float acc[2][8][4];
#pragma unroll
    for (int i = 0; i < 2; i++)
#pragma unroll
        for (int j = 0; j < 8; j++)
#pragma unroll
            for (int r = 0; r < 4; r++) acc[i][j][r] = 0.f;

    // stage layout: Ah 0..16K, Al 16K..32K, B 32K..48K   (128 rows x 128B each)
    auto load_stage = [&](int s, int k0) {
        uint32_t base = sb + s * STAGE_B;
#pragma unroll
        for (int j = 0; j < 4; j++) {
            int idx = tid + j * 256;                 // 0..1023
            int r = idx >> 3, c = idx & 7;
            uint32_t so = sw_off(r, c);
            size_t ao = (size_t)(row0 + r) * lda + k0 + c * 8;
            size_t bo = (size_t)(col0 + r) * ldb + k0 + c * 8;
            cpasync16(base + so,           Ah + ao);
            cpasync16(base + 16384 + so,   Al + ao);
            cpasync16(base + 32768 + so,   B + bo);
        }
        CP_COMMIT();
    };

    load_stage(0, kbeg);

    const int a_row = wm * 32 + ((lane >> 3) & 1) * 8 + (lane & 7);   // + mi*16
    const int b_row = wn * 64 + (lane >> 4) * 8 + (lane & 7);         // + j*16

    for (int it = 0; it < kn; it++) {
        if (it + 1 < kn) {
            load_stage((it + 1) & 1, kbeg + (it + 1) * 64);
            CP_WAIT1();
        } else {
            CP_WAIT0();
        }
        __syncthreads();
        uint32_t base = sb + (it & 1) * STAGE_B;
#pragma unroll
        for (int kk = 0; kk < 4; kk++) {
            uint32_t ah[2][4], al[2][4], bb[8][2];
#pragma unroll
            for (int mi = 0; mi < 2; mi++) {
                int r = a_row + mi * 16;
                int c = kk * 2 + (lane >> 4);
                uint32_t so = sw_off(r, c);
                LDSM4(ah[mi], base + so);
                LDSM4(al[mi], base + 16384 + so);
            }
#pragma unroll
            for (int j = 0; j < 4; j++) {
                int r = b_row + j * 16;
                int c = kk * 2 + ((lane >> 3) & 1);
                uint32_t so = sw_off(r, c);
                uint32_t t[4];
                LDSM4(t, base + 32768 + so);
                bb[2 * j][0] = t[0]; bb[2 * j][1] = t[1];
                bb[2 * j + 1][0] = t[2]; bb[2 * j + 1][1] = t[3];
            }
#pragma unroll
            for (int mi = 0; mi < 2; mi++)
#pragma unroll
                for (int nj = 0; nj < 8; nj++) {
                    mma16816(acc[mi][nj], ah[mi], bb[nj]);
                    mma16816(acc[mi][nj], al[mi], bb[nj]);
                }
        }
        __syncthreads();   // protect the stage next prefetch will overwrite
    }

    if (EPI == 0) C += (size_t)blockIdx.z * zstride;

#pragma unroll
    for (int mi = 0; mi < 2; mi++) {
        int row = row0 + wm * 32 + mi * 16 + (lane >> 2);
#pragma unroll
        for (int nj = 0; nj < 8; nj++) {
            int col = col0 + wn * 64 + nj * 8 + (lane & 3) * 2;
            float* a = acc[mi][nj];
            if (EPI == 0) {
                *(float2*)&C[(size_t)row * ldc + col]       = make_float2(a[0], a[1]);
                *(float2*)&C[(size_t)(row + 8) * ldc + col] = make_float2(a[2], a[3]);
            } else if (EPI == 1) {
                float b0 = bias[col], b1 = bias[col + 1];
                float v0 = a[0] + b0, v1 = a[1] + b1, v2 = a[2] + b0, v3 = a[3] + b1;
                v0 = (v0 > 20.f) ? v0 : log1pf(expf(v0));
                v1 = (v1 > 20.f) ? v1 : log1pf(expf(v1));
                v2 = (v2 > 20.f) ? v2 : log1pf(expf(v2));
                v3 = (v3 > 20.f) ? v3 : log1pf(expf(v3));
                *(float2*)&C[(size_t)row * ldc + col]       = make_float2(v0, v1);
                *(float2*)&C[(size_t)(row + 8) * ldc + col] = make_float2(v2, v3);
            } else if (EPI == 2) {
                atomicAdd(&C[(size_t)row * ldc + col],           a[0]);
                atomicAdd(&C[(size_t)row * ldc + col + 1],       a[1]);
                atomicAdd(&C[(size_t)(row + 8) * ldc + col],     a[2]);
                atomicAdd(&C[(size_t)(row + 8) * ldc + col + 1], a[3]);
            } else {  // EPI == 3: xz epilogue. cols < DINNER raw; cols >= DINNER -> silu -> g_zs
                if (col < DINNER) {
                    *(float2*)&C[(size_t)row * ldc + col]       = make_float2(a[0], a[1]);
                    *(float2*)&C[(size_t)(row + 8) * ldc + col] = make_float2(a[2], a[3]);
                } else {
                    int zc = col - DINNER;
                    float s0 = a[0] / (1.f + __expf(-a[0]));
                    float s1 = a[1] / (1.f + __expf(-a[1]));
                    float s2 = a[2] / (1.f + __expf(-a[2]));
                    float s3 = a[3] / (1.f + __expf(-a[3]));
                    *(float2*)&g_zs[(size_t)row * DINNER + zc]       = make_float2(s0, s1);
                    *(float2*)&g_zs[(size_t)(row + 8) * DINNER + zc] = make_float2(s2, s3);
                }
            }
        }
    }
}

// ---------------- reduce 4 split-K buffers into out ----------------
__global__ void reduce4(const float* __restrict__ src, float* __restrict__ dst, int n4) {
    int i = blockIdx.x * blockDim.x + threadIdx.x;
    if (i >= n4) return;
    const float4* s = (const float4*)src;
    float4 a = s[i], b = s[i + n4], c = s[i + 2 * n4], d = s[i + 3 * n4];
    float4 r = make_float4(a.x + b.x + c.x + d.x, a.y + b.y + c.y + d.y,
                           a.z + b.z + c.z + d.z, a.w + b.w + c.w + d.w);
    ((float4*)dst)[i] = r;
}

// ---------------- elementwise split (fp32 -> fp16 hi/lo) ----------------
__global__ void cvt_split(const float* __restrict__ src,
                          __half* __restrict__ h, __half* __restrict__ l, int n)
{
    int i = blockIdx.x * blockDim.x + threadIdx.x;
    if (i >= n) return;
    float v = src[i];
    __half hi = __float2half_rn(v);
    h[i] = hi;
    l[i] = __float2half_rn(v - __half2float(hi));
}

// dt_lo slice of padded xdbl -> split arrays [2048][64]
__global__ void cvt_dt()
{
    int i = blockIdx.x * blockDim.x + threadIdx.x;   // < NTOK*64
    int t = i >> 6, c = i & 63;
    float v = g_xdbl[(size_t)t * XDBL_LD + c];
    __half hi = __float2half_rn(v);
    g_dth[i] = hi;
    g_dtl[i] = __float2half_rn(v - __half2float(hi));
}

// ---------------- transpose + convert:  W[K][N] -> T[Npad][K] (fp16, pad zero) ----------------
__global__ void transpose_cvt(const float* __restrict__ W, int K, int N,
                              __half* __restrict__ T)
{
    __shared__ float t[32][33];
    int bx = blockIdx.x, by = blockIdx.y;
    int tx = threadIdx.x, ty0 = threadIdx.y;
#pragma unroll
    for (int s = 0; s < 4; s++) {
        int ty = ty0 + s * 8;
        int col = bx * 32 + tx;          // n
        int row = by * 32 + ty;          // k
        t[ty][tx] = (col < N) ? W[(size_t)row * N + col] : 0.f;
    }
    __syncthreads();
#pragma unroll
    for (int s = 0; s < 4; s++) {
        int ty = ty0 + s * 8;
        int n = bx * 32 + ty;
        int k = by * 32 + tx;
        T[(size_t)n * K + k] = __float2half_rn(t[tx][ty]);
    }
}

// ---------------- zero fill ----------------
__global__ void zero_kernel(float* __restrict__ p, int n) {
    int i = blockIdx.x * blockDim.x + threadIdx.x;
    if (i < n) p[i] = 0.f;
}

// ---------------- conv + SiLU -> fp32 u + fp16 split ----------------
__global__ void conv_silu(const float* __restrict__ ck, const float* __restrict__ cb)
{
    int idx = blockIdx.x * blockDim.x + threadIdx.x;
    if (idx >= NTOK * DINNER) return;
    int d  = idx & (DINNER - 1);
    int bt = idx >> 11;
    int t  = bt & (SEQL - 1);

    float acc = cb[d];
#pragma unroll
    for (int w = 0; w < DCONV; w++) {
        int tt = t - (DCONV - 1) + w;
        if (tt >= 0)
            acc = fmaf(ck[w * DINNER + d],
                       g_xz[(size_t)(bt - (DCONV - 1) + w) * (2 * DINNER) + d], acc);
    }
    float u = acc / (1.f + __expf(-acc));
    g_u[idx] = u;
    __half hi = __float2half_rn(u);
    g_uh[idx] = hi;
    g_ul[idx] = __float2half_rn(u - __half2float(hi));
}

// ---------------- chunked scan: phase 1 (chunk end-states, h0=0), smem B ----------------
__global__ __launch_bounds__(256) void scan_phase1(const float* __restrict__ A_log)
{
    __shared__ float sB[CLEN * DSTATE];    // 8 KB
    int tid = threadIdx.x;
    int ch = blockIdx.x * 16 + (tid >> 4);   // 0..4095
    int n = tid & 15;
    int c = blockIdx.y;
    int b = ch >> 11;
    int d = ch & (DINNER - 1);

    const float* xd = g_xdbl + (size_t)(b * SEQL + c * CLEN) * XDBL_LD;
    for (int i = tid; i < CLEN * DSTATE; i += 256)
        sB[i] = xd[(i >> 4) * XDBL_LD + DTRANK + (i & 15)];
    __syncthreads();

    float a = -expf(A_log[d * DSTATE + n]);
    float h = 0.f, sd = 0.f;

    const float* dptr = g_delta + (size_t)(b * SEQL + c * CLEN) * DINNER + d;
    const float* uptr = g_u     + (size_t)(b * SEQL + c * CLEN) * DINNER + d;

    for (int t = 0; t < CLEN; t++) {
        float delta = dptr[(size_t)t * DINNER];
        float uv    = uptr[(size_t)t * DINNER];
        float Bn    = sB[(t << 4) | n];
        h = __expf(delta * a) * h + delta * uv * Bn;
        sd += delta;
    }
    size_t idx = ((size_t)(b * DINNER + d) * DSTATE + n);
    g_hend[idx * NCHUNK + c] = h;
    if (n == 0) g_sumd[(size_t)(b * DINNER + d) * NCHUNK + c] = sd;
}

// ---------------- chunked scan: combine (sequential over 8 chunks) ----------------
__global__ void scan_combine(const float* __restrict__ A_log)
{
    int i = blockIdx.x * blockDim.x + threadIdx.x;     // < BATCH*DINNER*DSTATE
    if (i >= BATCH * DINNER * DSTATE) return;
    int n = i & 15;
    int d = (i >> 4) & (DINNER - 1);
    int bd = i >> 4;                                    // b*DINNER + d

    float a = -expf(A_log[d * DSTATE + n]);
    float H = 0.f;
#pragma unroll
    for (int c = 0; c < NCHUNK; c++) {
        g_h0[(size_t)i * NCHUNK + c] = H;
        float S = g_sumd[(size_t)bd * NCHUNK + c];
        H = __expf(a * S) * H + g_hend[(size_t)i * NCHUNK + c];
    }
}

// ---------------- chunked scan: phase 2 (y with true h0), smem B+C ----------------
__global__ __launch_bounds__(256) void scan_phase2(
    const float* __restrict__ A_log, const float* __restrict__ Dp)
{
    __shared__ float sBC[CLEN * 2 * DSTATE];   // 16 KB: [t][0..15]=B, [t][16..31]=C
    int tid = threadIdx.x;
    int ch = blockIdx.x * 16 + (tid >> 4);
    int n = tid & 15;
    int c = blockIdx.y;
    int b = ch >> 11;
    int d = ch & (DINNER - 1);

    const float* xd = g_xdbl + (size_t)(b * SEQL + c * CLEN) * XDBL_LD;
    for (int i = tid; i < CLEN * 2 * DSTATE; i += 256)
        sBC[i] = xd[(i >> 5) * XDBL_LD + DTRANK + (i & 31)];
    __syncthreads();

    float a = -expf(A_log[d * DSTATE + n]);
    float Dd = Dp[d];
    float h = g_h0[((size_t)(b * DINNER + d) * DSTATE + n) * NCHUNK + c];

    const float* dptr = g_delta + (size_t)(b * SEQL + c * CLEN) * DINNER + d;
    const float* uptr = g_u     + (size_t)(b * SEQL + c * CLEN) * DINNER + d;
    const float* zptr = g_zs    + (size_t)(b * SEQL + c * CLEN) * DINNER + d;
    __half* yh = g_yh + (size_t)(b * SEQL + c * CLEN) * DINNER + d;
    __half* yl = g_yl + (size_t)(b * SEQL + c * CLEN) * DINNER + d;

    for (int t = 0; t < CLEN; t++) {
        float delta = dptr[(size_t)t * DINNER];
        float uv    = uptr[(size_t)t * DINNER];
        float Bn    = sBC[(t << 5) | n];
        float Cn    = sBC[(t << 5) | 16 | n];

        h = __expf(delta * a) * h + delta * uv * Bn;

        float p = h * Cn;
        p += __shfl_xor_sync(0xffffffffu, p, 8);
        p += __shfl_xor_sync(0xffffffffu, p, 4);
        p += __shfl_xor_sync(0xffffffffu, p, 2);
        p += __shfl_xor_sync(0xffffffffu, p, 1);

        if (n == 0) {
            float v = (p + uv * Dd) * zptr[(size_t)t * DINNER];
            __half hi = __float2half_rn(v);
            yh[(size_t)t * DINNER] = hi;
            yl[(size_t)t * DINNER] = __float2half_rn(v - __half2float(hi));
        }
    }
}

// ---------------- launch ----------------
extern "C" void kernel_launch(void* const* d_in, const int* in_sizes, int n_in,
                              void* d_out, int out_size)
{
    (void)in_sizes; (void)n_in; (void)out_size;
    const float* x     = (const float*)d_in[0];
    const float* W_in  = (const float*)d_in[1];
    const float* ck    = (const float*)d_in[2];
    const float* cb    = (const float*)d_in[3];
    const float* W_x   = (const float*)d_in[4];
    const float* W_dt  = (const float*)d_in[5];
    const float* b_dt  = (const float*)d_in[6];
    const float* W_out = (const float*)d_in[7];
    const float* A_log = (const float*)d_in[8];
    const float* Dp    = (const float*)d_in[9];
    float* out = (float*)d_out;

    cudaFuncSetAttribute(mma_gemm<0>, cudaFuncAttributeMaxDynamicSharedMemorySize, MG_SMEM);
    cudaFuncSetAttribute(mma_gemm<1>, cudaFuncAttributeMaxDynamicSharedMemorySize, MG_SMEM);
    cudaFuncSetAttribute(mma_gemm<2>, cudaFuncAttributeMaxDynamicSharedMemorySize, MG_SMEM);
    cudaFuncSetAttribute(mma_gemm<3>, cudaFuncAttributeMaxDynamicSharedMemorySize, MG_SMEM);

    float *p_xz, *p_xdbl, *p_delta, *p_osplit;
    cudaGetSymbolAddress((void**)&p_xz,    g_xz);
    cudaGetSymbolAddress((void**)&p_xdbl,  g_xdbl);
    cudaGetSymbolAddress((void**)&p_delta, g_delta);
    cudaGetSymbolAddress((void**)&p_osplit, g_osplit);
    __half *xh, *xl, *uh, *ul, *yh, *yl, *dth, *dtl;
    __half *wint, *wxt, *wdtt, *wot;
    cudaGetSymbolAddress((void**)&xh, g_xh);     cudaGetSymbolAddress((void**)&xl, g_xl);
    cudaGetSymbolAddress((void**)&uh, g_uh);     cudaGetSymbolAddress((void**)&ul, g_ul);
    cudaGetSymbolAddress((void**)&yh, g_yh);     cudaGetSymbolAddress((void**)&yl, g_yl);
    cudaGetSymbolAddress((void**)&dth, g_dth);   cudaGetSymbolAddress((void**)&dtl, g_dtl);
    cudaGetSymbolAddress((void**)&wint, g_wint);
    cudaGetSymbolAddress((void**)&wxt, g_wxt);
    cudaGetSymbolAddress((void**)&wdtt, g_wdtt);
    cudaGetSymbolAddress((void**)&wot, g_wot);

    // launch #1..#3: prep
    cvt_split<<<(NTOK * DMODEL + 255) / 256, 256>>>(x, xh, xl, NTOK * DMODEL);
    transpose_cvt<<<dim3(2 * DINNER / 32, DMODEL / 32), dim3(32, 8)>>>(W_in, DMODEL, 2 * DINNER, wint);
    transpose_cvt<<<dim3(DMODEL / 32, DINNER / 32), dim3(32, 8)>>>(W_out, DINNER, DMODEL, wot);

    // launch #4: xz = x @ W_in : M=2048, N=4096, K=1024; z half -> silu -> g_zs
    mma_gemm<3><<<dim3(32, 16, 1), 256, MG_SMEM>>>(
        xh, xl, DMODEL, wint, DMODEL, p_xz, 2 * DINNER, DMODEL, 1, nullptr, 0);

    // conv + silu -> u (fp32 + fp16 splits)
    conv_silu<<<(NTOK * DINNER) / 256, 256>>>(ck, cb);

    // x_dbl = u @ W_x : M=2048, N=128(pad of 96), K=2048, split-K=8 atomics
    zero_kernel<<<(NTOK * XDBL_LD) / 256, 256>>>(p_xdbl, NTOK * XDBL_LD);
    transpose_cvt<<<dim3(XDBL_LD / 32, DINNER / 32), dim3(32, 8)>>>(W_x, DINNER, DTRANK + 2 * DSTATE, wxt);
    mma_gemm<2><<<dim3(1, 16, 8), 256, MG_SMEM>>>(
        uh, ul, DINNER, wxt, DINNER, p_xdbl, XDBL_LD, DINNER, 8, nullptr, 0);

    // delta = softplus(dt_lo @ W_dt + b_dt) : M=2048, N=2048, K=64 (single k-tile)
    cvt_dt<<<(NTOK * DTRANK) / 256, 256>>>();
    transpose_cvt<<<dim3(DINNER / 32, DTRANK / 32), dim3(32, 8)>>>(W_dt, DTRANK, DINNER, wdtt);
    mma_gemm<1><<<dim3(16, 16, 1), 256, MG_SMEM>>>(
        dth, dtl, DTRANK, wdtt, DTRANK, p_delta, DINNER, DTRANK, 1, b_dt, 0);

    // chunked selective scan
    scan_phase1<<<dim3((BATCH * DINNER) / 16, NCHUNK), 256>>>(A_log);
    scan_combine<<<(BATCH * DINNER * DSTATE) / 256, 256>>>(A_log);
    scan_phase2<<<dim3((BATCH * DINNER) / 16, NCHUNK), 256>>>(A_log, Dp);

    // out = y @ W_out : M=2048, N=1024, K=2048, split-K=4 -> buffers -> reduce
    mma_gemm<0><<<dim3(8, 16, 4), 256, MG_SMEM>>>(
        yh, yl, DINNER, wot, DINNER, p_osplit, DMODEL, DINNER, 4, nullptr, NTOK * DMODEL);
    reduce4<<<(NTOK * DMODEL / 4 + 255) / 256, 256>>>(p_osplit, out, NTOK * DMODEL / 4);
}

// round 10
// speedup vs baseline: 1.2752x; 1.0883x over previous
#include <cuda_runtime.h>
#include <cuda_fp16.h>
#include <math.h>
#include <stdint.h>

// ---------------- problem constants ----------------
#define BATCH   2
#define SEQL    1024
#define DMODEL  1024
#define DINNER  2048
#define DSTATE  16
#define DCONV   4
#define DTRANK  64
#define NTOK    (BATCH * SEQL)          // 2048
#define XDBL_LD 128                     // padded (dt 0..63 | B 64..79 | C 80..95 | pad)
#define NCHUNK  8
#define CLEN    (SEQL / NCHUNK)         // 128

// ---------------- PTX helpers (portable: sm_80-era features only) ----------------
__device__ __forceinline__ uint32_t smem_to_u32(const void* p) {
    uint32_t a;
    asm("{ .reg .u64 t; cvta.to.shared.u64 t, %1; cvt.u32.u64 %0, t; }" : "=r"(a) : "l"(p));
    return a;
}
__device__ __forceinline__ void cpasync16(uint32_t s, const void* g) {
    asm volatile("cp.async.cg.shared.global [%0], [%1], 16;" :: "r"(s), "l"(g));
}
#define CP_COMMIT()  asm volatile("cp.async.commit_group;" ::: "memory")
#define CP_WAIT0()   asm volatile("cp.async.wait_group 0;" ::: "memory")
#define CP_WAIT1()   asm volatile("cp.async.wait_group 1;" ::: "memory")
#define LDSM4(r, addr) \
    asm volatile("ldmatrix.sync.aligned.m8n8.x4.shared.b16 {%0,%1,%2,%3}, [%4];" \
        : "=r"((r)[0]), "=r"((r)[1]), "=r"((r)[2]), "=r"((r)[3]) : "r"(addr))

__device__ __forceinline__ void mma16816(float* d, const uint32_t* a, const uint32_t* b) {
    asm volatile(
        "mma.sync.aligned.m16n8k16.row.col.f32.f16.f16.f32 "
        "{%0,%1,%2,%3}, {%4,%5,%6,%7}, {%8,%9}, {%0,%1,%2,%3};"
        : "+f"(d[0]), "+f"(d[1]), "+f"(d[2]), "+f"(d[3])
        : "r"(a[0]), "r"(a[1]), "r"(a[2]), "r"(a[3]), "r"(b[0]), "r"(b[1]));
}

// swizzled byte offset of 16B chunk c (0..7) in row r (row = 128 bytes = 8 chunks)
__device__ __forceinline__ uint32_t sw_off(int r, int c) {
    return (uint32_t)(r * 128 + ((c ^ (r & 7)) << 4));
}
__device__ __forceinline__ float silu(float v) { return v / (1.f + __expf(-v)); }

// ---------------- scratch (device globals) ----------------
__device__ float g_xz[(size_t)NTOK * 2 * DINNER];     // u_raw (z half unused)
__device__ float g_u[(size_t)NTOK * DINNER];          // fp32 u for the scan
__device__ float g_zs[(size_t)NTOK * DINNER];
__device__ float g_xdbl[(size_t)NTOK * XDBL_LD];
__device__ float g_delta[(size_t)NTOK * DINNER];
__device__ float g_osplit[(size_t)4 * NTOK * DMODEL]; // split-K buffers for out GEMM
// chunked-scan state
__device__ float g_hend[(size_t)BATCH * DINNER * DSTATE * NCHUNK];
__device__ float g_h0[(size_t)BATCH * DINNER * DSTATE * NCHUNK];
__device__ float g_sumd[(size_t)BATCH * DINNER * NCHUNK];

// A-side fp16 (hi + lo split where 2-pass is used)
__device__ __half g_xh[(size_t)NTOK * DMODEL],   g_xl[(size_t)NTOK * DMODEL];
__device__ __half g_uh[(size_t)NTOK * DINNER],   g_ul[(size_t)NTOK * DINNER];
__device__ __half g_yh[(size_t)NTOK * DINNER];                       // single-pass
__device__ __half g_dth[(size_t)NTOK * DTRANK],  g_dtl[(size_t)NTOK * DTRANK];
// B-side: transposed single fp16 weights: [N][K] row-major (K contiguous)
__device__ __half g_wint[(size_t)2 * DINNER * DMODEL];
__device__ __half g_wxt[(size_t)XDBL_LD * DINNER];
__device__ __half g_wdtt[(size_t)DINNER * DTRANK];
__device__ __half g_wot[(size_t)DMODEL * DINNER];

// ---------------- mma.sync fp16 GEMM, K-tile 64, 2-stage pipeline ----------------
// C[M,N] = (Ah [+ Al])[M,K] @ B[K,N], B given transposed [N][K], fp32 accum.
// TWO=1: two-pass A split; TWO=0: single A operand (Al unused).
// EPI 0: store (+zstride per blockIdx.z), 1: softplus(acc+bias), 2: atomicAdd,
// EPI 3: store u-half raw; z-half -> silu to g_zs
#define STAGE_B 49152
#define MG_SMEM (2 * STAGE_B)
template <int EPI, int TWO>
__global__ __launch_bounds__(256, 2) void mma_gemm(
    const __half* __restrict__ Ah, const __half* __restrict__ Al, int lda,
    const __half* __restrict__ B, int ldb,
    float* __restrict__ C, int ldc, int K, int KS, const float* __restrict__ bias,
    int zstride)
{
    extern __shared__ char smem[];
    uint32_t sb = smem_to_u32(smem);
    const int tid = threadIdx.x, lane = tid & 31, wid = tid >> 5;
    const int wm = wid & 3, wn = wid >> 2;          // warp tile: rows wm*32, cols wn*64
    const int row0 = blockIdx.y * 128, col0 = blockIdx.x * 128;
    const int kper = K / KS;
    const int kbeg = blockIdx.z * kper;
    const int kn = kper >> 6;                        // 64-wide k tiles

    float acc[2][8][4];
#pragma unroll
    for (int i = 0; i < 2; i++)
#pragma unroll
        for (int j = 0; j < 8; j++)
#pragma unroll
            for (int r = 0; r < 4; r++) acc[i][j][r] = 0.f;

    // stage layout: Ah 0..16K, Al 16K..32K, B 32K..48K   (128 rows x 128B each)
    auto load_stage = [&](int s, int k0) {
        uint32_t base = sb + s * STAGE_B;
#pragma unroll
        for (int j = 0; j < 4; j++) {
            int idx = tid + j * 256;                 // 0..1023
            int r = idx >> 3, c = idx & 7;
            uint32_t so = sw_off(r, c);
            size_t ao = (size_t)(row0 + r) * lda + k0 + c * 8;
            size_t bo = (size_t)(col0 + r) * ldb + k0 + c * 8;
            cpasync16(base + so,           Ah + ao);
            if (TWO) cpasync16(base + 16384 + so, Al + ao);
            cpasync16(base + 32768 + so,   B + bo);
        }
        CP_COMMIT();
    };

    load_stage(0, kbeg);

    const int a_row = wm * 32 + ((lane >> 3) & 1) * 8 + (lane & 7);   // + mi*16
    const int b_row = wn * 64 + (lane >> 4) * 8 + (lane & 7);         // + j*16

    for (int it = 0; it < kn; it++) {
        if (it + 1 < kn) {
            load_stage((it + 1) & 1, kbeg + (it + 1) * 64);
            CP_WAIT1();
        } else {
            CP_WAIT0();
        }
        __syncthreads();
        uint32_t base = sb + (it & 1) * STAGE_B;
#pragma unroll
        for (int kk = 0; kk < 4; kk++) {
            uint32_t ah[2][4], al[2][4], bb[8][2];
#pragma unroll
            for (int mi = 0; mi < 2; mi++) {
                int r = a_row + mi * 16;
                int c = kk * 2 + (lane >> 4);
                uint32_t so = sw_off(r, c);
                LDSM4(ah[mi], base + so);
                if (TWO) LDSM4(al[mi], base + 16384 + so);
            }
#pragma unroll
            for (int j = 0; j < 4; j++) {
                int r = b_row + j * 16;
                int c = kk * 2 + ((lane >> 3) & 1);
                uint32_t so = sw_off(r, c);
                uint32_t t[4];
                LDSM4(t, base + 32768 + so);
                bb[2 * j][0] = t[0]; bb[2 * j][1] = t[1];
                bb[2 * j + 1][0] = t[2]; bb[2 * j + 1][1] = t[3];
            }
#pragma unroll
            for (int mi = 0; mi < 2; mi++)
#pragma unroll
                for (int nj = 0; nj < 8; nj++) {
                    mma16816(acc[mi][nj], ah[mi], bb[nj]);
                    if (TWO) mma16816(acc[mi][nj], al[mi], bb[nj]);
                }
        }
        __syncthreads();   // protect the stage next prefetch will overwrite
    }

    if (EPI == 0) C += (size_t)blockIdx.z * zstride;

#pragma unroll
    for (int mi = 0; mi < 2; mi++) {
        int row = row0 + wm * 32 + mi * 16 + (lane >> 2);
#pragma unroll
        for (int nj = 0; nj < 8; nj++) {
            int col = col0 + wn * 64 + nj * 8 + (lane & 3) * 2;
            float* a = acc[mi][nj];
            if (EPI == 0) {
                *(float2*)&C[(size_t)row * ldc + col]       = make_float2(a[0], a[1]);
                *(float2*)&C[(size_t)(row + 8) * ldc + col] = make_float2(a[2], a[3]);
            } else if (EPI == 1) {
                float b0 = bias[col], b1 = bias[col + 1];
                float v0 = a[0] + b0, v1 = a[1] + b1, v2 = a[2] + b0, v3 = a[3] + b1;
                v0 = (v0 > 20.f) ? v0 : log1pf(expf(v0));
                v1 = (v1 > 20.f) ? v1 : log1pf(expf(v1));
                v2 = (v2 > 20.f) ? v2 : log1pf(expf(v2));
                v3 = (v3 > 20.f) ? v3 : log1pf(expf(v3));
                *(float2*)&C[(size_t)row * ldc + col]       = make_float2(v0, v1);
                *(float2*)&C[(size_t)(row + 8) * ldc + col] = make_float2(v2, v3);
            } else if (EPI == 2) {
                atomicAdd(&C[(size_t)row * ldc + col],           a[0]);
                atomicAdd(&C[(size_t)row * ldc + col + 1],       a[1]);
                atomicAdd(&C[(size_t)(row + 8) * ldc + col],     a[2]);
                atomicAdd(&C[(size_t)(row + 8) * ldc + col + 1], a[3]);
            } else {  // EPI == 3: xz epilogue. cols < DINNER raw; cols >= DINNER -> silu -> g_zs
                if (col < DINNER) {
                    *(float2*)&C[(size_t)row * ldc + col]       = make_float2(a[0], a[1]);
                    *(float2*)&C[(size_t)(row + 8) * ldc + col] = make_float2(a[2], a[3]);
                } else {
                    int zc = col - DINNER;
                    *(float2*)&g_zs[(size_t)row * DINNER + zc]       = make_float2(silu(a[0]), silu(a[1]));
                    *(float2*)&g_zs[(size_t)(row + 8) * DINNER + zc] = make_float2(silu(a[2]), silu(a[3]));
                }
            }
        }
    }
}

// ---------------- reduce 4 split-K buffers into out ----------------
__global__ void reduce4(const float* __restrict__ src, float* __restrict__ dst, int n4) {
    int i = blockIdx.x * blockDim.x + threadIdx.x;
    if (i >= n4) return;
    const float4* s = (const float4*)src;
    float4 a = s[i], b = s[i + n4], c = s[i + 2 * n4], d = s[i + 3 * n4];
    float4 r = make_float4(a.x + b.x + c.x + d.x, a.y + b.y + c.y + d.y,
                           a.z + b.z + c.z + d.z, a.w + b.w + c.w + d.w);
    ((float4*)dst)[i] = r;
}

// ---------------- vectorized split (fp32 -> fp16 hi/lo), 4 elems/thread ----------------
__global__ void cvt_split(const float* __restrict__ src,
                          __half* __restrict__ h, __half* __restrict__ l, int n4)
{
    int i = blockIdx.x * blockDim.x + threadIdx.x;
    if (i >= n4) return;
    float4 v = ((const float4*)src)[i];
    __half h0 = __float2half_rn(v.x), h1 = __float2half_rn(v.y);
    __half h2 = __float2half_rn(v.z), h3 = __float2half_rn(v.w);
    __half2 hh0 = __halves2half2(h0, h1), hh1 = __halves2half2(h2, h3);
    __half2 ll0 = __halves2half2(__float2half_rn(v.x - __half2float(h0)),
                                 __float2half_rn(v.y - __half2float(h1)));
    __half2 ll1 = __halves2half2(__float2half_rn(v.z - __half2float(h2)),
                                 __float2half_rn(v.w - __half2float(h3)));
    ((__half2*)h)[i * 2]     = hh0;
    ((__half2*)h)[i * 2 + 1] = hh1;
    ((__half2*)l)[i * 2]     = ll0;
    ((__half2*)l)[i * 2 + 1] = ll1;
}

// dt_lo slice of padded xdbl -> split arrays [2048][64]
__global__ void cvt_dt()
{
    int i = blockIdx.x * blockDim.x + threadIdx.x;   // < NTOK*64
    int t = i >> 6, c = i & 63;
    float v = g_xdbl[(size_t)t * XDBL_LD + c];
    __half hi = __float2half_rn(v);
    g_dth[i] = hi;
    g_dtl[i] = __float2half_rn(v - __half2float(hi));
}

// ---------------- transpose + convert:  W[K][N] -> T[Npad][K] (fp16, pad zero) ----------------
__global__ void transpose_cvt(const float* __restrict__ W, int K, int N,
                              __half* __restrict__ T)
{
    __shared__ float t[32][33];
    int bx = blockIdx.x, by = blockIdx.y;
    int tx = threadIdx.x, ty0 = threadIdx.y;
#pragma unroll
    for (int s = 0; s < 4; s++) {
        int ty = ty0 + s * 8;
        int col = bx * 32 + tx;          // n
        int row = by * 32 + ty;          // k
        t[ty][tx] = (col < N) ? W[(size_t)row * N + col] : 0.f;
    }
    __syncthreads();
#pragma unroll
    for (int s = 0; s < 4; s++) {
        int ty = ty0 + s * 8;
        int n = bx * 32 + ty;
        int k = by * 32 + tx;
        T[(size_t)n * K + k] = __float2half_rn(t[tx][ty]);
    }
}

// ---------------- zero fill ----------------
__global__ void zero_kernel(float* __restrict__ p, int n) {
    int i = blockIdx.x * blockDim.x + threadIdx.x;
    if (i < n) p[i] = 0.f;
}

// ---------------- conv + SiLU -> fp32 u + fp16 split, 4 channels/thread ----------------
__global__ void conv_silu(const float* __restrict__ ck, const float* __restrict__ cb)
{
    int idx = blockIdx.x * blockDim.x + threadIdx.x;   // < NTOK*DINNER/4
    if (idx >= NTOK * DINNER / 4) return;
    int dq = idx & (DINNER / 4 - 1);
    int bt = idx >> 9;
    int t  = bt & (SEQL - 1);
    int d  = dq * 4;

    float4 acc = *(const float4*)&cb[d];
#pragma unroll
    for (int w = 0; w < DCONV; w++) {
        int tt = t - (DCONV - 1) + w;
        if (tt >= 0) {
            float4 k = *(const float4*)&ck[w * DINNER + d];
            float4 v = *(const float4*)&g_xz[(size_t)(bt - (DCONV - 1) + w) * (2 * DINNER) + d];
            acc.x = fmaf(k.x, v.x, acc.x);
            acc.y = fmaf(k.y, v.y, acc.y);
            acc.z = fmaf(k.z, v.z, acc.z);
            acc.w = fmaf(k.w, v.w, acc.w);
        }
    }
    float4 u = make_float4(silu(acc.x), silu(acc.y), silu(acc.z), silu(acc.w));
    size_t o = (size_t)bt * DINNER + d;
    *(float4*)&g_u[o] = u;
    __half h0 = __float2half_rn(u.x), h1 = __float2half_rn(u.y);
    __half h2 = __float2half_rn(u.z), h3 = __float2half_rn(u.w);
    *(__half2*)&g_uh[o]     = __halves2half2(h0, h1);
    *(__half2*)&g_uh[o + 2] = __halves2half2(h2, h3);
    *(__half2*)&g_ul[o]     = __halves2half2(__float2half_rn(u.x - __half2float(h0)),
                                             __float2half_rn(u.y - __half2float(h1)));
    *(__half2*)&g_ul[o + 2] = __halves2half2(__float2half_rn(u.z - __half2float(h2)),
                                             __float2half_rn(u.w - __half2float(h3)));
}

// ---------------- chunked scan: phase 1 (chunk end-states, h0=0), smem B ----------------
__global__ __launch_bounds__(256) void scan_phase1(const float* __restrict__ A_log)
{
    __shared__ float sB[CLEN * DSTATE];    // 8 KB
    int tid = threadIdx.x;
    int ch = blockIdx.x * 16 + (tid >> 4);   // 0..4095
    int n = tid & 15;
    int c = blockIdx.y;
    int b = ch >> 11;
    int d = ch & (DINNER - 1);

    const float* xd = g_xdbl + (size_t)(b * SEQL + c * CLEN) * XDBL_LD;
    for (int i = tid; i < CLEN * DSTATE; i += 256)
        sB[i] = xd[(i >> 4) * XDBL_LD + DTRANK + (i & 15)];
    __syncthreads();

    float a = -expf(A_log[d * DSTATE + n]);
    float h = 0.f, sd = 0.f;

    const float* dptr = g_delta + (size_t)(b * SEQL + c * CLEN) * DINNER + d;
    const float* uptr = g_u     + (size_t)(b * SEQL + c * CLEN) * DINNER + d;

    for (int t = 0; t < CLEN; t++) {
        float delta = dptr[(size_t)t * DINNER];
        float uv    = uptr[(size_t)t * DINNER];
        float Bn    = sB[(t << 4) | n];
        h = __expf(delta * a) * h + delta * uv * Bn;
        sd += delta;
    }
    size_t idx = ((size_t)(b * DINNER + d) * DSTATE + n);
    g_hend[idx * NCHUNK + c] = h;
    if (n == 0) g_sumd[(size_t)(b * DINNER + d) * NCHUNK + c] = sd;
}

// ---------------- chunked scan: combine (sequential over 8 chunks) ----------------
__global__ void scan_combine(const float* __restrict__ A_log)
{
    int i = blockIdx.x * blockDim.x + threadIdx.x;     // < BATCH*DINNER*DSTATE
    if (i >= BATCH * DINNER * DSTATE) return;
    int n = i & 15;
    int d = (i >> 4) & (DINNER - 1);
    int bd = i >> 4;                                    // b*DINNER + d

    float a = -expf(A_log[d * DSTATE + n]);
    float H = 0.f;
#pragma unroll
    for (int c = 0; c < NCHUNK; c++) {
        g_h0[(size_t)i * NCHUNK + c] = H;
        float S = g_sumd[(size_t)bd * NCHUNK + c];
        H = __expf(a * S) * H + g_hend[(size_t)i * NCHUNK + c];
    }
}

// ---------------- chunked scan: phase 2 (y with true h0), smem B+C ----------------
__global__ __launch_bounds__(256) void scan_phase2(
    const float* __restrict__ A_log, const float* __restrict__ Dp)
{
    __shared__ float sBC[CLEN * 2 * DSTATE];   // 16 KB: [t][0..15]=B, [t][16..31]=C
    int tid = threadIdx.x;
    int ch = blockIdx.x * 16 + (tid >> 4);
    int n = tid & 15;
    int c = blockIdx.y;
    int b = ch >> 11;
    int d = ch & (DINNER - 1);

    const float* xd = g_xdbl + (size_t)(b * SEQL + c * CLEN) * XDBL_LD;
    for (int i = tid; i < CLEN * 2 * DSTATE; i += 256)
        sBC[i] = xd[(i >> 5) * XDBL_LD + DTRANK + (i & 31)];
    __syncthreads();

    float a = -expf(A_log[d * DSTATE + n]);
    float Dd = Dp[d];
    float h = g_h0[((size_t)(b * DINNER + d) * DSTATE + n) * NCHUNK + c];

    const float* dptr = g_delta + (size_t)(b * SEQL + c * CLEN) * DINNER + d;
    const float* uptr = g_u     + (size_t)(b * SEQL + c * CLEN) * DINNER + d;
    const float* zptr = g_zs    + (size_t)(b * SEQL + c * CLEN) * DINNER + d;
    __half* yh = g_yh + (size_t)(b * SEQL + c * CLEN) * DINNER + d;

    for (int t = 0; t < CLEN; t++) {
        float delta = dptr[(size_t)t * DINNER];
        float uv    = uptr[(size_t)t * DINNER];
        float Bn    = sBC[(t << 5) | n];
        float Cn    = sBC[(t << 5) | 16 | n];

        h = __expf(delta * a) * h + delta * uv * Bn;

        float p = h * Cn;
        p += __shfl_xor_sync(0xffffffffu, p, 8);
        p += __shfl_xor_sync(0xffffffffu, p, 4);
        p += __shfl_xor_sync(0xffffffffu, p, 2);
        p += __shfl_xor_sync(0xffffffffu, p, 1);

        if (n == 0) {
            float v = (p + uv * Dd) * zptr[(size_t)t * DINNER];
            yh[(size_t)t * DINNER] = __float2half_rn(v);
        }
    }
}

// ---------------- launch ----------------
extern "C" void kernel_launch(void* const* d_in, const int* in_sizes, int n_in,
                              void* d_out, int out_size)
{
    (void)in_sizes; (void)n_in; (void)out_size;
    const float* x     = (const float*)d_in[0];
    const float* W_in  = (const float*)d_in[1];
    const float* ck    = (const float*)d_in[2];
    const float* cb    = (const float*)d_in[3];
    const float* W_x   = (const float*)d_in[4];
    const float* W_dt  = (const float*)d_in[5];
    const float* b_dt  = (const float*)d_in[6];
    const float* W_out = (const float*)d_in[7];
    const float* A_log = (const float*)d_in[8];
    const float* Dp    = (const float*)d_in[9];
    float* out = (float*)d_out;

    cudaFuncSetAttribute((const void*)mma_gemm<0, 0>, cudaFuncAttributeMaxDynamicSharedMemorySize, MG_SMEM);
    cudaFuncSetAttribute((const void*)mma_gemm<1, 1>, cudaFuncAttributeMaxDynamicSharedMemorySize, MG_SMEM);
    cudaFuncSetAttribute((const void*)mma_gemm<2, 1>, cudaFuncAttributeMaxDynamicSharedMemorySize, MG_SMEM);
    cudaFuncSetAttribute((const void*)mma_gemm<3, 1>, cudaFuncAttributeMaxDynamicSharedMemorySize, MG_SMEM);

    float *p_xz, *p_xdbl, *p_delta, *p_osplit;
    cudaGetSymbolAddress((void**)&p_xz,    g_xz);
    cudaGetSymbolAddress((void**)&p_xdbl,  g_xdbl);
    cudaGetSymbolAddress((void**)&p_delta, g_delta);
    cudaGetSymbolAddress((void**)&p_osplit, g_osplit);
    __half *xh, *xl, *uh, *ul, *yh, *dth, *dtl;
    __half *wint, *wxt, *wdtt, *wot;
    cudaGetSymbolAddress((void**)&xh, g_xh);     cudaGetSymbolAddress((void**)&xl, g_xl);
    cudaGetSymbolAddress((void**)&uh, g_uh);     cudaGetSymbolAddress((void**)&ul, g_ul);
    cudaGetSymbolAddress((void**)&yh, g_yh);
    cudaGetSymbolAddress((void**)&dth, g_dth);   cudaGetSymbolAddress((void**)&dtl, g_dtl);
    cudaGetSymbolAddress((void**)&wint, g_wint);
    cudaGetSymbolAddress((void**)&wxt, g_wxt);
    cudaGetSymbolAddress((void**)&wdtt, g_wdtt);
    cudaGetSymbolAddress((void**)&wot, g_wot);

    // launch #1..#3: prep
    cvt_split<<<(NTOK * DMODEL / 4 + 255) / 256, 256>>>(x, xh, xl, NTOK * DMODEL / 4);
    transpose_cvt<<<dim3(2 * DINNER / 32, DMODEL / 32), dim3(32, 8)>>>(W_in, DMODEL, 2 * DINNER, wint);
    transpose_cvt<<<dim3(DMODEL / 32, DINNER / 32), dim3(32, 8)>>>(W_out, DINNER, DMODEL, wot);

    // launch #4: xz = x @ W_in : M=2048, N=4096, K=1024; z half -> silu -> g_zs
    mma_gemm<3, 1><<<dim3(32, 16, 1), 256, MG_SMEM>>>(
        xh, xl, DMODEL, wint, DMODEL, p_xz, 2 * DINNER, DMODEL, 1, nullptr, 0);

    // conv + silu -> u (fp32 + fp16 splits), 4 channels/thread
    conv_silu<<<(NTOK * DINNER / 4) / 256, 256>>>(ck, cb);

    // x_dbl = u @ W_x : M=2048, N=128(pad of 96), K=2048, split-K=8 atomics
    zero_kernel<<<(NTOK * XDBL_LD) / 256, 256>>>(p_xdbl, NTOK * XDBL_LD);
    transpose_cvt<<<dim3(XDBL_LD / 32, DINNER / 32), dim3(32, 8)>>>(W_x, DINNER, DTRANK + 2 * DSTATE, wxt);
    mma_gemm<2, 1><<<dim3(1, 16, 8), 256, MG_SMEM>>>(
        uh, ul, DINNER, wxt, DINNER, p_xdbl, XDBL_LD, DINNER, 8, nullptr, 0);

    // delta = softplus(dt_lo @ W_dt + b_dt) : M=2048, N=2048, K=64 (single k-tile)
    cvt_dt<<<(NTOK * DTRANK) / 256, 256>>>();
    transpose_cvt<<<dim3(DINNER / 32, DTRANK / 32), dim3(32, 8)>>>(W_dt, DTRANK, DINNER, wdtt);
    mma_gemm<1, 1><<<dim3(16, 16, 1), 256, MG_SMEM>>>(
        dth, dtl, DTRANK, wdtt, DTRANK, p_delta, DINNER, DTRANK, 1, b_dt, 0);

    // chunked selective scan
    scan_phase1<<<dim3((BATCH * DINNER) / 16, NCHUNK), 256>>>(A_log);
    scan_combine<<<(BATCH * DINNER * DSTATE) / 256, 256>>>(A_log);
    scan_phase2<<<dim3((BATCH * DINNER) / 16, NCHUNK), 256>>>(A_log, Dp);

    // out = y @ W_out : M=2048, N=1024, K=2048, split-K=4 (single-pass A) -> reduce
    mma_gemm<0, 0><<<dim3(8, 16, 4), 256, MG_SMEM>>>(
        yh, nullptr, DINNER, wot, DINNER, p_osplit, DMODEL, DINNER, 4, nullptr, NTOK * DMODEL);
    reduce4<<<(NTOK * DMODEL / 4 + 255) / 256, 256>>>(p_osplit, out, NTOK * DMODEL / 4);
}

// round 11
// speedup vs baseline: 1.4147x; 1.1094x over previous
#include <cuda_runtime.h>
#include <cuda_fp16.h>
#include <math.h>
#include <stdint.h>

// ---------------- problem constants ----------------
#define BATCH   2
#define SEQL    1024
#define DMODEL  1024
#define DINNER  2048
#define DSTATE  16
#define DCONV   4
#define DTRANK  64
#define NTOK    (BATCH * SEQL)          // 2048
#define XDBL_LD 128                     // padded (dt 0..63 | B 64..79 | C 80..95 | pad)
#define NCHUNK  8
#define CLEN    (SEQL / NCHUNK)         // 128

// ---------------- PTX helpers (portable: sm_80-era features only) ----------------
__device__ __forceinline__ uint32_t smem_to_u32(const void* p) {
    uint32_t a;
    asm("{ .reg .u64 t; cvta.to.shared.u64 t, %1; cvt.u32.u64 %0, t; }" : "=r"(a) : "l"(p));
    return a;
}
__device__ __forceinline__ void cpasync16(uint32_t s, const void* g) {
    asm volatile("cp.async.cg.shared.global [%0], [%1], 16;" :: "r"(s), "l"(g));
}
#define CP_COMMIT()  asm volatile("cp.async.commit_group;" ::: "memory")
#define CP_WAIT0()   asm volatile("cp.async.wait_group 0;" ::: "memory")
#define CP_WAIT1()   asm volatile("cp.async.wait_group 1;" ::: "memory")
#define LDSM4(r, addr) \
    asm volatile("ldmatrix.sync.aligned.m8n8.x4.shared.b16 {%0,%1,%2,%3}, [%4];" \
        : "=r"((r)[0]), "=r"((r)[1]), "=r"((r)[2]), "=r"((r)[3]) : "r"(addr))

__device__ __forceinline__ void mma16816(float* d, const uint32_t* a, const uint32_t* b) {
    asm volatile(
        "mma.sync.aligned.m16n8k16.row.col.f32.f16.f16.f32 "
        "{%0,%1,%2,%3}, {%4,%5,%6,%7}, {%8,%9}, {%0,%1,%2,%3};"
        : "+f"(d[0]), "+f"(d[1]), "+f"(d[2]), "+f"(d[3])
        : "r"(a[0]), "r"(a[1]), "r"(a[2]), "r"(a[3]), "r"(b[0]), "r"(b[1]));
}

// swizzled byte offset of 16B chunk c (0..7) in row r (row = 128 bytes = 8 chunks)
__device__ __forceinline__ uint32_t sw_off(int r, int c) {
    return (uint32_t)(r * 128 + ((c ^ (r & 7)) << 4));
}
__device__ __forceinline__ float silu(float v) { return v / (1.f + __expf(-v)); }

// ---------------- scratch (device globals) ----------------
__device__ float g_xz[(size_t)NTOK * 2 * DINNER];     // u_raw (z half unused)
__device__ float g_u[(size_t)NTOK * DINNER];          // fp32 u for the scan
__device__ float g_zs[(size_t)NTOK * DINNER];
__device__ float g_xdbl[(size_t)NTOK * XDBL_LD];
__device__ float g_delta[(size_t)NTOK * DINNER];
__device__ float g_osplit[(size_t)4 * NTOK * DMODEL]; // split-K buffers for out GEMM
// chunked-scan state
__device__ float g_hend[(size_t)BATCH * DINNER * DSTATE * NCHUNK];
__device__ float g_h0[(size_t)BATCH * DINNER * DSTATE * NCHUNK];
__device__ float g_sumd[(size_t)BATCH * DINNER * NCHUNK];

// A-side fp16 (hi + lo split where 2-pass is used)
__device__ __half g_xh[(size_t)NTOK * DMODEL];                       // single-pass
__device__ __half g_uh[(size_t)NTOK * DINNER],   g_ul[(size_t)NTOK * DINNER];
__device__ __half g_yh[(size_t)NTOK * DINNER];                       // single-pass
__device__ __half g_dth[(size_t)NTOK * DTRANK],  g_dtl[(size_t)NTOK * DTRANK];
// B-side: transposed single fp16 weights: [N][K] row-major (K contiguous)
__device__ __half g_wint[(size_t)2 * DINNER * DMODEL];
__device__ __half g_wxt[(size_t)XDBL_LD * DINNER];
__device__ __half g_wdtt[(size_t)DINNER * DTRANK];
__device__ __half g_wot[(size_t)DMODEL * DINNER];

// ---------------- mma.sync fp16 GEMM, K-tile 64, 2-stage pipeline ----------------
// C[M,N] = (Ah [+ Al])[M,K] @ B[K,N], B given transposed [N][K], fp32 accum.
// TWO=1: two-pass A split; TWO=0: single A operand (Al unused).
// EPI 0: store (+zstride per blockIdx.z), 1: softplus(acc+bias), 2: atomicAdd,
// EPI 3: store u-half raw; z-half -> silu to g_zs
#define STAGE_B 49152
#define MG_SMEM (2 * STAGE_B)
template <int EPI, int TWO>
__global__ __launch_bounds__(256, 2) void mma_gemm(
    const __half* __restrict__ Ah, const __half* __restrict__ Al, int lda,
    const __half* __restrict__ B, int ldb,
    float* __restrict__ C, int ldc, int K, int KS, const float* __restrict__ bias,
    int zstride)
{
    extern __shared__ char smem[];
    uint32_t sb = smem_to_u32(smem);
    const int tid = threadIdx.x, lane = tid & 31, wid = tid >> 5;
    const int wm = wid & 3, wn = wid >> 2;          // warp tile: rows wm*32, cols wn*64
    const int row0 = blockIdx.y * 128, col0 = blockIdx.x * 128;
    const int kper = K / KS;
    const int kbeg = blockIdx.z * kper;
    const int kn = kper >> 6;                        // 64-wide k tiles

    float acc[2][8][4];
#pragma unroll
    for (int i = 0; i < 2; i++)
#pragma unroll
        for (int j = 0; j < 8; j++)
#pragma unroll
            for (int r = 0; r < 4; r++) acc[i][j][r] = 0.f;

    // stage layout: Ah 0..16K, Al 16K..32K, B 32K..48K   (128 rows x 128B each)
    auto load_stage = [&](int s, int k0) {
        uint32_t base = sb + s * STAGE_B;
#pragma unroll
        for (int j = 0; j < 4; j++) {
            int idx = tid + j * 256;                 // 0..1023
            int r = idx >> 3, c = idx & 7;
            uint32_t so = sw_off(r, c);
            size_t ao = (size_t)(row0 + r) * lda + k0 + c * 8;
            size_t bo = (size_t)(col0 + r) * ldb + k0 + c * 8;
            cpasync16(base + so,           Ah + ao);
            if (TWO) cpasync16(base + 16384 + so, Al + ao);
            cpasync16(base + 32768 + so,   B + bo);
        }
        CP_COMMIT();
    };

    load_stage(0, kbeg);

    const int a_row = wm * 32 + ((lane >> 3) & 1) * 8 + (lane & 7);   // + mi*16
    const int b_row = wn * 64 + (lane >> 4) * 8 + (lane & 7);         // + j*16

    for (int it = 0; it < kn; it++) {
        if (it + 1 < kn) {
            load_stage((it + 1) & 1, kbeg + (it + 1) * 64);
            CP_WAIT1();
        } else {
            CP_WAIT0();
        }
        __syncthreads();
        uint32_t base = sb + (it & 1) * STAGE_B;
#pragma unroll
        for (int kk = 0; kk < 4; kk++) {
            uint32_t ah[2][4], al[2][4], bb[8][2];
#pragma unroll
            for (int mi = 0; mi < 2; mi++) {
                int r = a_row + mi * 16;
                int c = kk * 2 + (lane >> 4);
                uint32_t so = sw_off(r, c);
                LDSM4(ah[mi], base + so);
                if (TWO) LDSM4(al[mi], base + 16384 + so);
            }
#pragma unroll
            for (int j = 0; j < 4; j++) {
                int r = b_row + j * 16;
                int c = kk * 2 + ((lane >> 3) & 1);
                uint32_t so = sw_off(r, c);
                uint32_t t[4];
                LDSM4(t, base + 32768 + so);
                bb[2 * j][0] = t[0]; bb[2 * j][1] = t[1];
                bb[2 * j + 1][0] = t[2]; bb[2 * j + 1][1] = t[3];
            }
#pragma unroll
            for (int mi = 0; mi < 2; mi++)
#pragma unroll
                for (int nj = 0; nj < 8; nj++) {
                    mma16816(acc[mi][nj], ah[mi], bb[nj]);
                    if (TWO) mma16816(acc[mi][nj], al[mi], bb[nj]);
                }
        }
        __syncthreads();   // protect the stage next prefetch will overwrite
    }

    if (EPI == 0) C += (size_t)blockIdx.z * zstride;

#pragma unroll
    for (int mi = 0; mi < 2; mi++) {
        int row = row0 + wm * 32 + mi * 16 + (lane >> 2);
#pragma unroll
        for (int nj = 0; nj < 8; nj++) {
            int col = col0 + wn * 64 + nj * 8 + (lane & 3) * 2;
            float* a = acc[mi][nj];
            if (EPI == 0) {
                *(float2*)&C[(size_t)row * ldc + col]       = make_float2(a[0], a[1]);
                *(float2*)&C[(size_t)(row + 8) * ldc + col] = make_float2(a[2], a[3]);
            } else if (EPI == 1) {
                float b0 = bias[col], b1 = bias[col + 1];
                float v0 = a[0] + b0, v1 = a[1] + b1, v2 = a[2] + b0, v3 = a[3] + b1;
                v0 = (v0 > 20.f) ? v0 : log1pf(expf(v0));
                v1 = (v1 > 20.f) ? v1 : log1pf(expf(v1));
                v2 = (v2 > 20.f) ? v2 : log1pf(expf(v2));
                v3 = (v3 > 20.f) ? v3 : log1pf(expf(v3));
                *(float2*)&C[(size_t)row * ldc + col]       = make_float2(v0, v1);
                *(float2*)&C[(size_t)(row + 8) * ldc + col] = make_float2(v2, v3);
            } else if (EPI == 2) {
                atomicAdd(&C[(size_t)row * ldc + col],           a[0]);
                atomicAdd(&C[(size_t)row * ldc + col + 1],       a[1]);
                atomicAdd(&C[(size_t)(row + 8) * ldc + col],     a[2]);
                atomicAdd(&C[(size_t)(row + 8) * ldc + col + 1], a[3]);
            } else {  // EPI == 3: xz epilogue. cols < DINNER raw; cols >= DINNER -> silu -> g_zs
                if (col < DINNER) {
                    *(float2*)&C[(size_t)row * ldc + col]       = make_float2(a[0], a[1]);
                    *(float2*)&C[(size_t)(row + 8) * ldc + col] = make_float2(a[2], a[3]);
                } else {
                    int zc = col - DINNER;
                    *(float2*)&g_zs[(size_t)row * DINNER + zc]       = make_float2(silu(a[0]), silu(a[1]));
                    *(float2*)&g_zs[(size_t)(row + 8) * DINNER + zc] = make_float2(silu(a[2]), silu(a[3]));
                }
            }
        }
    }
}

// ---------------- reduce 4 split-K buffers into out ----------------
__global__ void reduce4(const float* __restrict__ src, float* __restrict__ dst, int n4) {
    int i = blockIdx.x * blockDim.x + threadIdx.x;
    if (i >= n4) return;
    const float4* s = (const float4*)src;
    float4 a = s[i], b = s[i + n4], c = s[i + 2 * n4], d = s[i + 3 * n4];
    float4 r = make_float4(a.x + b.x + c.x + d.x, a.y + b.y + c.y + d.y,
                           a.z + b.z + c.z + d.z, a.w + b.w + c.w + d.w);
    ((float4*)dst)[i] = r;
}

// ---------------- vectorized convert (fp32 -> fp16 hi only), 4 elems/thread ----------------
__global__ void cvt_h(const float* __restrict__ src, __half* __restrict__ h, int n4)
{
    int i = blockIdx.x * blockDim.x + threadIdx.x;
    if (i >= n4) return;
    float4 v = ((const float4*)src)[i];
    ((__half2*)h)[i * 2]     = __halves2half2(__float2half_rn(v.x), __float2half_rn(v.y));
    ((__half2*)h)[i * 2 + 1] = __halves2half2(__float2half_rn(v.z), __float2half_rn(v.w));
}

// dt_lo slice of padded xdbl -> split arrays [2048][64]
__global__ void cvt_dt()
{
    int i = blockIdx.x * blockDim.x + threadIdx.x;   // < NTOK*64
    int t = i >> 6, c = i & 63;
    float v = g_xdbl[(size_t)t * XDBL_LD + c];
    __half hi = __float2half_rn(v);
    g_dth[i] = hi;
    g_dtl[i] = __float2half_rn(v - __half2float(hi));
}

// ---------------- transpose + convert:  W[K][N] -> T[Npad][K] (fp16, pad zero) ----------------
__global__ void transpose_cvt(const float* __restrict__ W, int K, int N,
                              __half* __restrict__ T)
{
    __shared__ float t[32][33];
    int bx = blockIdx.x, by = blockIdx.y;
    int tx = threadIdx.x, ty0 = threadIdx.y;
#pragma unroll
    for (int s = 0; s < 4; s++) {
        int ty = ty0 + s * 8;
        int col = bx * 32 + tx;          // n
        int row = by * 32 + ty;          // k
        t[ty][tx] = (col < N) ? W[(size_t)row * N + col] : 0.f;
    }
    __syncthreads();
#pragma unroll
    for (int s = 0; s < 4; s++) {
        int ty = ty0 + s * 8;
        int n = bx * 32 + ty;
        int k = by * 32 + tx;
        T[(size_t)n * K + k] = __float2half_rn(t[tx][ty]);
    }
}

// ---------------- zero fill ----------------
__global__ void zero_kernel(float* __restrict__ p, int n) {
    int i = blockIdx.x * blockDim.x + threadIdx.x;
    if (i < n) p[i] = 0.f;
}

// ---------------- conv + SiLU -> fp32 u + fp16 split, 4 channels/thread ----------------
__global__ void conv_silu(const float* __restrict__ ck, const float* __restrict__ cb)
{
    int idx = blockIdx.x * blockDim.x + threadIdx.x;   // < NTOK*DINNER/4
    if (idx >= NTOK * DINNER / 4) return;
    int dq = idx & (DINNER / 4 - 1);
    int bt = idx >> 9;
    int t  = bt & (SEQL - 1);
    int d  = dq * 4;

    float4 acc = *(const float4*)&cb[d];
#pragma unroll
    for (int w = 0; w < DCONV; w++) {
        int tt = t - (DCONV - 1) + w;
        if (tt >= 0) {
            float4 k = *(const float4*)&ck[w * DINNER + d];
            float4 v = *(const float4*)&g_xz[(size_t)(bt - (DCONV - 1) + w) * (2 * DINNER) + d];
            acc.x = fmaf(k.x, v.x, acc.x);
            acc.y = fmaf(k.y, v.y, acc.y);
            acc.z = fmaf(k.z, v.z, acc.z);
            acc.w = fmaf(k.w, v.w, acc.w);
        }
    }
    float4 u = make_float4(silu(acc.x), silu(acc.y), silu(acc.z), silu(acc.w));
    size_t o = (size_t)bt * DINNER + d;
    *(float4*)&g_u[o] = u;
    __half h0 = __float2half_rn(u.x), h1 = __float2half_rn(u.y);
    __half h2 = __float2half_rn(u.z), h3 = __float2half_rn(u.w);
    *(__half2*)&g_uh[o]     = __halves2half2(h0, h1);
    *(__half2*)&g_uh[o + 2] = __halves2half2(h2, h3);
    *(__half2*)&g_ul[o]     = __halves2half2(__float2half_rn(u.x - __half2float(h0)),
                                             __float2half_rn(u.y - __half2float(h1)));
    *(__half2*)&g_ul[o + 2] = __halves2half2(__float2half_rn(u.z - __half2float(h2)),
                                             __float2half_rn(u.w - __half2float(h3)));
}

// ---------------- chunked scan: phase 1 (chunk end-states, h0=0), smem B ----------------
__global__ __launch_bounds__(256) void scan_phase1(const float* __restrict__ A_log)
{
    __shared__ float sB[CLEN * DSTATE];    // 8 KB
    int tid = threadIdx.x;
    int ch = blockIdx.x * 16 + (tid >> 4);   // 0..4095
    int n = tid & 15;
    int c = blockIdx.y;
    int b = ch >> 11;
    int d = ch & (DINNER - 1);

    const float* xd = g_xdbl + (size_t)(b * SEQL + c * CLEN) * XDBL_LD;
    for (int i = tid; i < CLEN * DSTATE; i += 256)
        sB[i] = xd[(i >> 4) * XDBL_LD + DTRANK + (i & 15)];
    __syncthreads();

    float a = -expf(A_log[d * DSTATE + n]);
    float h = 0.f, sd = 0.f;

    const float* dptr = g_delta + (size_t)(b * SEQL + c * CLEN) * DINNER + d;
    const float* uptr = g_u     + (size_t)(b * SEQL + c * CLEN) * DINNER + d;

    for (int t = 0; t < CLEN; t++) {
        float delta = dptr[(size_t)t * DINNER];
        float uv    = uptr[(size_t)t * DINNER];
        float Bn    = sB[(t << 4) | n];
        h = __expf(delta * a) * h + delta * uv * Bn;
        sd += delta;
    }
    size_t idx = ((size_t)(b * DINNER + d) * DSTATE + n);
    g_hend[idx * NCHUNK + c] = h;
    if (n == 0) g_sumd[(size_t)(b * DINNER + d) * NCHUNK + c] = sd;
}

// ---------------- chunked scan: combine (sequential over 8 chunks) ----------------
__global__ void scan_combine(const float* __restrict__ A_log)
{
    int i = blockIdx.x * blockDim.x + threadIdx.x;     // < BATCH*DINNER*DSTATE
    if (i >= BATCH * DINNER * DSTATE) return;
    int n = i & 15;
    int d = (i >> 4) & (DINNER - 1);
    int bd = i >> 4;                                    // b*DINNER + d

    float a = -expf(A_log[d * DSTATE + n]);
    float H = 0.f;
#pragma unroll
    for (int c = 0; c < NCHUNK; c++) {
        g_h0[(size_t)i * NCHUNK + c] = H;
        float S = g_sumd[(size_t)bd * NCHUNK + c];
        H = __expf(a * S) * H + g_hend[(size_t)i * NCHUNK + c];
    }
}

// ---------------- chunked scan: phase 2 (y with true h0), smem B+C ----------------
__global__ __launch_bounds__(256) void scan_phase2(
    const float* __restrict__ A_log, const float* __restrict__ Dp)
{
    __shared__ float sBC[CLEN * 2 * DSTATE];   // 16 KB: [t][0..15]=B, [t][16..31]=C
    int tid = threadIdx.x;
    int ch = blockIdx.x * 16 + (tid >> 4);
    int n = tid & 15;
    int c = blockIdx.y;
    int b = ch >> 11;
    int d = ch & (DINNER - 1);

    const float* xd = g_xdbl + (size_t)(b * SEQL + c * CLEN) * XDBL_LD;
    for (int i = tid; i < CLEN * 2 * DSTATE; i += 256)
        sBC[i] = xd[(i >> 5) * XDBL_LD + DTRANK + (i & 31)];
    __syncthreads();

    float a = -expf(A_log[d * DSTATE + n]);
    float Dd = Dp[d];
    float h = g_h0[((size_t)(b * DINNER + d) * DSTATE + n) * NCHUNK + c];

    const float* dptr = g_delta + (size_t)(b * SEQL + c * CLEN) * DINNER + d;
    const float* uptr = g_u     + (size_t)(b * SEQL + c * CLEN) * DINNER + d;
    const float* zptr = g_zs    + (size_t)(b * SEQL + c * CLEN) * DINNER + d;
    __half* yh = g_yh + (size_t)(b * SEQL + c * CLEN) * DINNER + d;

    for (int t = 0; t < CLEN; t++) {
        float delta = dptr[(size_t)t * DINNER];
        float uv    = uptr[(size_t)t * DINNER];
        float Bn    = sBC[(t << 5) | n];
        float Cn    = sBC[(t << 5) | 16 | n];

        h = __expf(delta * a) * h + delta * uv * Bn;

        float p = h * Cn;
        p += __shfl_xor_sync(0xffffffffu, p, 8);
        p += __shfl_xor_sync(0xffffffffu, p, 4);
        p += __shfl_xor_sync(0xffffffffu, p, 2);
        p += __shfl_xor_sync(0xffffffffu, p, 1);

        if (n == 0) {
            float v = (p + uv * Dd) * zptr[(size_t)t * DINNER];
            yh[(size_t)t * DINNER] = __float2half_rn(v);
        }
    }
}

// ---------------- launch ----------------
extern "C" void kernel_launch(void* const* d_in, const int* in_sizes, int n_in,
                              void* d_out, int out_size)
{
    (void)in_sizes; (void)n_in; (void)out_size;
    const float* x     = (const float*)d_in[0];
    const float* W_in  = (const float*)d_in[1];
    const float* ck    = (const float*)d_in[2];
    const float* cb    = (const float*)d_in[3];
    const float* W_x   = (const float*)d_in[4];
    const float* W_dt  = (const float*)d_in[5];
    const float* b_dt  = (const float*)d_in[6];
    const float* W_out = (const float*)d_in[7];
    const float* A_log = (const float*)d_in[8];
    const float* Dp    = (const float*)d_in[9];
    float* out = (float*)d_out;

    cudaFuncSetAttribute((const void*)mma_gemm<0, 0>, cudaFuncAttributeMaxDynamicSharedMemorySize, MG_SMEM);
    cudaFuncSetAttribute((const void*)mma_gemm<1, 1>, cudaFuncAttributeMaxDynamicSharedMemorySize, MG_SMEM);
    cudaFuncSetAttribute((const void*)mma_gemm<2, 1>, cudaFuncAttributeMaxDynamicSharedMemorySize, MG_SMEM);
    cudaFuncSetAttribute((const void*)mma_gemm<3, 0>, cudaFuncAttributeMaxDynamicSharedMemorySize, MG_SMEM);

    float *p_xz, *p_xdbl, *p_delta, *p_osplit;
    cudaGetSymbolAddress((void**)&p_xz,    g_xz);
    cudaGetSymbolAddress((void**)&p_xdbl,  g_xdbl);
    cudaGetSymbolAddress((void**)&p_delta, g_delta);
    cudaGetSymbolAddress((void**)&p_osplit, g_osplit);
    __half *xh, *uh, *ul, *yh, *dth, *dtl;
    __half *wint, *wxt, *wdtt, *wot;
    cudaGetSymbolAddress((void**)&xh, g_xh);
    cudaGetSymbolAddress((void**)&uh, g_uh);     cudaGetSymbolAddress((void**)&ul, g_ul);
    cudaGetSymbolAddress((void**)&yh, g_yh);
    cudaGetSymbolAddress((void**)&dth, g_dth);   cudaGetSymbolAddress((void**)&dtl, g_dtl);
    cudaGetSymbolAddress((void**)&wint, g_wint);
    cudaGetSymbolAddress((void**)&wxt, g_wxt);
    cudaGetSymbolAddress((void**)&wdtt, g_wdtt);
    cudaGetSymbolAddress((void**)&wot, g_wot);

    // launch #1..#3: prep
    cvt_h<<<(NTOK * DMODEL / 4 + 255) / 256, 256>>>(x, xh, NTOK * DMODEL / 4);
    transpose_cvt<<<dim3(2 * DINNER / 32, DMODEL / 32), dim3(32, 8)>>>(W_in, DMODEL, 2 * DINNER, wint);
    transpose_cvt<<<dim3(DMODEL / 32, DINNER / 32), dim3(32, 8)>>>(W_out, DINNER, DMODEL, wot);

    // launch #4: xz = x @ W_in : M=2048, N=4096, K=1024 (single-pass A); z -> silu -> g_zs
    mma_gemm<3, 0><<<dim3(32, 16, 1), 256, MG_SMEM>>>(
        xh, nullptr, DMODEL, wint, DMODEL, p_xz, 2 * DINNER, DMODEL, 1, nullptr, 0);

    // conv + silu -> u (fp32 + fp16 splits), 4 channels/thread
    conv_silu<<<(NTOK * DINNER / 4) / 256, 256>>>(ck, cb);

    // x_dbl = u @ W_x : M=2048, N=128(pad of 96), K=2048, split-K=8 atomics (2-pass A)
    zero_kernel<<<(NTOK * XDBL_LD) / 256, 256>>>(p_xdbl, NTOK * XDBL_LD);
    transpose_cvt<<<dim3(XDBL_LD / 32, DINNER / 32), dim3(32, 8)>>>(W_x, DINNER, DTRANK + 2 * DSTATE, wxt);
    mma_gemm<2, 1><<<dim3(1, 16, 8), 256, MG_SMEM>>>(
        uh, ul, DINNER, wxt, DINNER, p_xdbl, XDBL_LD, DINNER, 8, nullptr, 0);

    // delta = softplus(dt_lo @ W_dt + b_dt) : M=2048, N=2048, K=64 (2-pass A)
    cvt_dt<<<(NTOK * DTRANK) / 256, 256>>>();
    transpose_cvt<<<dim3(DINNER / 32, DTRANK / 32), dim3(32, 8)>>>(W_dt, DTRANK, DINNER, wdtt);
    mma_gemm<1, 1><<<dim3(16, 16, 1), 256, MG_SMEM>>>(
        dth, dtl, DTRANK, wdtt, DTRANK, p_delta, DINNER, DTRANK, 1, b_dt, 0);

    // chunked selective scan
    scan_phase1<<<dim3((BATCH * DINNER) / 16, NCHUNK), 256>>>(A_log);
    scan_combine<<<(BATCH * DINNER * DSTATE) / 256, 256>>>(A_log);
    scan_phase2<<<dim3((BATCH * DINNER) / 16, NCHUNK), 256>>>(A_log, Dp);

    // out = y @ W_out : M=2048, N=1024, K=2048, split-K=4 (single-pass A) -> reduce
    mma_gemm<0, 0><<<dim3(8, 16, 4), 256, MG_SMEM>>>(
        yh, nullptr, DINNER, wot, DINNER, p_osplit, DMODEL, DINNER, 4, nullptr, NTOK * DMODEL);
    reduce4<<<(NTOK * DMODEL / 4 + 255) / 256, 256>>>(p_osplit, out, NTOK * DMODEL / 4);
}

// round 12
// speedup vs baseline: 1.4869x; 1.0510x over previous
#include <cuda_runtime.h>
#include <cuda_fp16.h>
#include <math.h>
#include <stdint.h>

// ---------------- problem constants ----------------
#define BATCH   2
#define SEQL    1024
#define DMODEL  1024
#define DINNER  2048
#define DSTATE  16
#define DCONV   4
#define DTRANK  64
#define NTOK    (BATCH * SEQL)          // 2048
#define XDBL_LD 128                     // padded (dt 0..63 | B 64..79 | C 80..95 | pad)
#define NCHUNK  8
#define CLEN    (SEQL / NCHUNK)         // 128

// ---------------- PTX helpers (portable: sm_80-era features only) ----------------
__device__ __forceinline__ uint32_t smem_to_u32(const void* p) {
    uint32_t a;
    asm("{ .reg .u64 t; cvta.to.shared.u64 t, %1; cvt.u32.u64 %0, t; }" : "=r"(a) : "l"(p));
    return a;
}
__device__ __forceinline__ void cpasync16(uint32_t s, const void* g) {
    asm volatile("cp.async.cg.shared.global [%0], [%1], 16;" :: "r"(s), "l"(g));
}
#define CP_COMMIT()  asm volatile("cp.async.commit_group;" ::: "memory")
#define CP_WAIT0()   asm volatile("cp.async.wait_group 0;" ::: "memory")
#define CP_WAIT1()   asm volatile("cp.async.wait_group 1;" ::: "memory")
#define LDSM4(r, addr) \
    asm volatile("ldmatrix.sync.aligned.m8n8.x4.shared.b16 {%0,%1,%2,%3}, [%4];" \
        : "=r"((r)[0]), "=r"((r)[1]), "=r"((r)[2]), "=r"((r)[3]) : "r"(addr))

__device__ __forceinline__ void mma16816(float* d, const uint32_t* a, const uint32_t* b) {
    asm volatile(
        "mma.sync.aligned.m16n8k16.row.col.f32.f16.f16.f32 "
        "{%0,%1,%2,%3}, {%4,%5,%6,%7}, {%8,%9}, {%0,%1,%2,%3};"
        : "+f"(d[0]), "+f"(d[1]), "+f"(d[2]), "+f"(d[3])
        : "r"(a[0]), "r"(a[1]), "r"(a[2]), "r"(a[3]), "r"(b[0]), "r"(b[1]));
}

// swizzled byte offset of 16B chunk c (0..7) in row r (row = 128 bytes = 8 chunks)
__device__ __forceinline__ uint32_t sw_off(int r, int c) {
    return (uint32_t)(r * 128 + ((c ^ (r & 7)) << 4));
}
__device__ __forceinline__ float silu(float v) { return v / (1.f + __expf(-v)); }

// ---------------- scratch (device globals) ----------------
__device__ float g_xz[(size_t)NTOK * 2 * DINNER];     // u_raw (z half unused)
__device__ float g_u[(size_t)NTOK * DINNER];          // fp32 u for the scan
__device__ float g_zs[(size_t)NTOK * DINNER];
__device__ float g_xdbl[(size_t)NTOK * XDBL_LD];
__device__ float g_delta[(size_t)NTOK * DINNER];
__device__ float g_osplit[(size_t)4 * NTOK * DMODEL]; // split-K buffers (xdbl: 8x2048x128; out: 4x2048x1024)
// chunked-scan state
__device__ float g_hend[(size_t)BATCH * DINNER * DSTATE * NCHUNK];
__device__ float g_h0[(size_t)BATCH * DINNER * DSTATE * NCHUNK];
__device__ float g_sumd[(size_t)BATCH * DINNER * NCHUNK];

// A-side fp16
__device__ __half g_xh[(size_t)NTOK * DMODEL];                       // single-pass
__device__ __half g_uh[(size_t)NTOK * DINNER];                       // single-pass
__device__ __half g_yh[(size_t)NTOK * DINNER];                       // single-pass
__device__ __half g_dth[(size_t)NTOK * DTRANK],  g_dtl[(size_t)NTOK * DTRANK];  // 2-pass
// B-side: transposed single fp16 weights: [N][K] row-major (K contiguous)
__device__ __half g_wint[(size_t)2 * DINNER * DMODEL];
__device__ __half g_wxt[(size_t)XDBL_LD * DINNER];
__device__ __half g_wdtt[(size_t)DINNER * DTRANK];
__device__ __half g_wot[(size_t)DMODEL * DINNER];

// ---------------- mma.sync fp16 GEMM, K-tile 64, 2-stage pipeline ----------------
// C[M,N] = (Ah [+ Al])[M,K] @ B[K,N], B given transposed [N][K], fp32 accum.
// TWO=1: two-pass A split; TWO=0: single A operand (Al unused).
// EPI 0: store (+zstride per blockIdx.z), 1: softplus(acc+bias),
// EPI 3: store u-half raw; z-half -> silu to g_zs
#define STAGE_B 49152
#define MG_SMEM (2 * STAGE_B)
template <int EPI, int TWO>
__global__ __launch_bounds__(256, 2) void mma_gemm(
    const __half* __restrict__ Ah, const __half* __restrict__ Al, int lda,
    const __half* __restrict__ B, int ldb,
    float* __restrict__ C, int ldc, int K, int KS, const float* __restrict__ bias,
    int zstride)
{
    extern __shared__ char smem[];
    uint32_t sb = smem_to_u32(smem);
    const int tid = threadIdx.x, lane = tid & 31, wid = tid >> 5;
    const int wm = wid & 3, wn = wid >> 2;          // warp tile: rows wm*32, cols wn*64
    const int row0 = blockIdx.y * 128, col0 = blockIdx.x * 128;
    const int kper = K / KS;
    const int kbeg = blockIdx.z * kper;
    const int kn = kper >> 6;                        // 64-wide k tiles

    float acc[2][8][4];
#pragma unroll
    for (int i = 0; i < 2; i++)
#pragma unroll
        for (int j = 0; j < 8; j++)
#pragma unroll
            for (int r = 0; r < 4; r++) acc[i][j][r] = 0.f;

    // stage layout: Ah 0..16K, Al 16K..32K, B 32K..48K   (128 rows x 128B each)
    auto load_stage = [&](int s, int k0) {
        uint32_t base = sb + s * STAGE_B;
#pragma unroll
        for (int j = 0; j < 4; j++) {
            int idx = tid + j * 256;                 // 0..1023
            int r = idx >> 3, c = idx & 7;
            uint32_t so = sw_off(r, c);
            size_t ao = (size_t)(row0 + r) * lda + k0 + c * 8;
            size_t bo = (size_t)(col0 + r) * ldb + k0 + c * 8;
            cpasync16(base + so,           Ah + ao);
            if (TWO) cpasync16(base + 16384 + so, Al + ao);
            cpasync16(base + 32768 + so,   B + bo);
        }
        CP_COMMIT();
    };

    load_stage(0, kbeg);

    const int a_row = wm * 32 + ((lane >> 3) & 1) * 8 + (lane & 7);   // + mi*16
    const int b_row = wn * 64 + (lane >> 4) * 8 + (lane & 7);         // + j*16

    for (int it = 0; it < kn; it++) {
        if (it + 1 < kn) {
            load_stage((it + 1) & 1, kbeg + (it + 1) * 64);
            CP_WAIT1();
        } else {
            CP_WAIT0();
        }
        __syncthreads();
        uint32_t base = sb + (it & 1) * STAGE_B;
#pragma unroll
        for (int kk = 0; kk < 4; kk++) {
            uint32_t ah[2][4], al[2][4], bb[8][2];
#pragma unroll
            for (int mi = 0; mi < 2; mi++) {
                int r = a_row + mi * 16;
                int c = kk * 2 + (lane >> 4);
                uint32_t so = sw_off(r, c);
                LDSM4(ah[mi], base + so);
                if (TWO) LDSM4(al[mi], base + 16384 + so);
            }
#pragma unroll
            for (int j = 0; j < 4; j++) {
                int r = b_row + j * 16;
                int c = kk * 2 + ((lane >> 3) & 1);
                uint32_t so = sw_off(r, c);
                uint32_t t[4];
                LDSM4(t, base + 32768 + so);
                bb[2 * j][0] = t[0]; bb[2 * j][1] = t[1];
                bb[2 * j + 1][0] = t[2]; bb[2 * j + 1][1] = t[3];
            }
#pragma unroll
            for (int mi = 0; mi < 2; mi++)
#pragma unroll
                for (int nj = 0; nj < 8; nj++) {
                    mma16816(acc[mi][nj], ah[mi], bb[nj]);
                    if (TWO) mma16816(acc[mi][nj], al[mi], bb[nj]);
                }
        }
        __syncthreads();   // protect the stage next prefetch will overwrite
    }

    if (EPI == 0) C += (size_t)blockIdx.z * zstride;

#pragma unroll
    for (int mi = 0; mi < 2; mi++) {
        int row = row0 + wm * 32 + mi * 16 + (lane >> 2);
#pragma unroll
        for (int nj = 0; nj < 8; nj++) {
            int col = col0 + wn * 64 + nj * 8 + (lane & 3) * 2;
            float* a = acc[mi][nj];
            if (EPI == 0) {
                *(float2*)&C[(size_t)row * ldc + col]       = make_float2(a[0], a[1]);
                *(float2*)&C[(size_t)(row + 8) * ldc + col] = make_float2(a[2], a[3]);
            } else if (EPI == 1) {
                float b0 = bias[col], b1 = bias[col + 1];
                float v0 = a[0] + b0, v1 = a[1] + b1, v2 = a[2] + b0, v3 = a[3] + b1;
                v0 = (v0 > 20.f) ? v0 : log1pf(expf(v0));
                v1 = (v1 > 20.f) ? v1 : log1pf(expf(v1));
                v2 = (v2 > 20.f) ? v2 : log1pf(expf(v2));
                v3 = (v3 > 20.f) ? v3 : log1pf(expf(v3));
                *(float2*)&C[(size_t)row * ldc + col]       = make_float2(v0, v1);
                *(float2*)&C[(size_t)(row + 8) * ldc + col] = make_float2(v2, v3);
            } else {  // EPI == 3: xz epilogue. cols < DINNER raw; cols >= DINNER -> silu -> g_zs
                if (col < DINNER) {
                    *(float2*)&C[(size_t)row * ldc + col]       = make_float2(a[0], a[1]);
                    *(float2*)&C[(size_t)(row + 8) * ldc + col] = make_float2(a[2], a[3]);
                } else {
                    int zc = col - DINNER;
                    *(float2*)&g_zs[(size_t)row * DINNER + zc]       = make_float2(silu(a[0]), silu(a[1]));
                    *(float2*)&g_zs[(size_t)(row + 8) * DINNER + zc] = make_float2(silu(a[2]), silu(a[3]));
                }
            }
        }
    }
}

// ---------------- reduce 4 split-K buffers into out ----------------
__global__ void reduce4(const float* __restrict__ src, float* __restrict__ dst, int n4) {
    int i = blockIdx.x * blockDim.x + threadIdx.x;
    if (i >= n4) return;
    const float4* s = (const float4*)src;
    float4 a = s[i], b = s[i + n4], c = s[i + 2 * n4], d = s[i + 3 * n4];
    float4 r = make_float4(a.x + b.x + c.x + d.x, a.y + b.y + c.y + d.y,
                           a.z + b.z + c.z + d.z, a.w + b.w + c.w + d.w);
    ((float4*)dst)[i] = r;
}

// ---------------- reduce 8 split-K xdbl buffers -> g_xdbl + dt hi/lo split ----------------
__global__ void reduce8_xdbl(const float* __restrict__ src) {
    int i = blockIdx.x * blockDim.x + threadIdx.x;   // < NTOK*XDBL_LD/4
    const int n4 = NTOK * XDBL_LD / 4;
    if (i >= n4) return;
    const float4* s = (const float4*)src;
    float4 r = s[i];
#pragma unroll
    for (int k = 1; k < 8; k++) {
        float4 v = s[i + k * n4];
        r.x += v.x; r.y += v.y; r.z += v.z; r.w += v.w;
    }
    ((float4*)g_xdbl)[i] = r;
    int t  = i >> 5;          // row (32 float4 chunks per 128-col row)
    int cq = i & 31;
    if (cq < DTRANK / 4) {    // dt region
        int c = cq * 4;
        __half h0 = __float2half_rn(r.x), h1 = __float2half_rn(r.y);
        __half h2 = __float2half_rn(r.z), h3 = __float2half_rn(r.w);
        size_t o = (size_t)t * DTRANK + c;
        *(__half2*)&g_dth[o]     = __halves2half2(h0, h1);
        *(__half2*)&g_dth[o + 2] = __halves2half2(h2, h3);
        *(__half2*)&g_dtl[o]     = __halves2half2(__float2half_rn(r.x - __half2float(h0)),
                                                  __float2half_rn(r.y - __half2float(h1)));
        *(__half2*)&g_dtl[o + 2] = __halves2half2(__float2half_rn(r.z - __half2float(h2)),
                                                  __float2half_rn(r.w - __half2float(h3)));
    }
}

// ---------------- vectorized convert (fp32 -> fp16 hi only), 4 elems/thread ----------------
__global__ void cvt_h(const float* __restrict__ src, __half* __restrict__ h, int n4)
{
    int i = blockIdx.x * blockDim.x + threadIdx.x;
    if (i >= n4) return;
    float4 v = ((const float4*)src)[i];
    ((__half2*)h)[i * 2]     = __halves2half2(__float2half_rn(v.x), __float2half_rn(v.y));
    ((__half2*)h)[i * 2 + 1] = __halves2half2(__float2half_rn(v.z), __float2half_rn(v.w));
}

// ---------------- transpose + convert:  W[K][N] -> T[Npad][K] (fp16, pad zero) ----------------
__device__ __forceinline__ void trans_body(const float* __restrict__ W, int K, int N,
                                           __half* __restrict__ T, int bx, int by,
                                           float t[32][33])
{
    int tx = threadIdx.x, ty0 = threadIdx.y;
#pragma unroll
    for (int s = 0; s < 4; s++) {
        int ty = ty0 + s * 8;
        int col = bx * 32 + tx;          // n
        int row = by * 32 + ty;          // k
        t[ty][tx] = (col < N) ? W[(size_t)row * N + col] : 0.f;
    }
    __syncthreads();
#pragma unroll
    for (int s = 0; s < 4; s++) {
        int ty = ty0 + s * 8;
        int n = bx * 32 + ty;
        int k = by * 32 + tx;
        T[(size_t)n * K + k] = __float2half_rn(t[tx][ty]);
    }
}

__global__ void transpose_cvt(const float* __restrict__ W, int K, int N,
                              __half* __restrict__ T)
{
    __shared__ float t[32][33];
    trans_body(W, K, N, T, blockIdx.x, blockIdx.y, t);
}

// combined transpose for W_out (2048x1024 -> wot), W_x (2048x96 -> wxt[128][2048]),
// W_dt (64x2048 -> wdtt[2048][64])
#define TB_OUT (32 * 64)     // 2048 blocks
#define TB_WX  (4 * 64)      // 256 blocks
#define TB_WDT (64 * 2)      // 128 blocks
__global__ void transpose_cvt3(const float* __restrict__ Wout,
                               const float* __restrict__ Wx,
                               const float* __restrict__ Wdt,
                               __half* __restrict__ Tout,
                               __half* __restrict__ Txt,
                               __half* __restrict__ Tdtt)
{
    __shared__ float t[32][33];
    int bid = blockIdx.x;
    if (bid < TB_OUT) {
        trans_body(Wout, DINNER, DMODEL, Tout, bid & 31, bid >> 5, t);
    } else if (bid < TB_OUT + TB_WX) {
        bid -= TB_OUT;
        trans_body(Wx, DINNER, DTRANK + 2 * DSTATE, Txt, bid & 3, bid >> 2, t);
    } else {
        bid -= TB_OUT + TB_WX;
        trans_body(Wdt, DTRANK, DINNER, Tdtt, bid & 63, bid >> 6, t);
    }
}

// ---------------- conv + SiLU -> fp32 u + fp16 hi, 4 channels/thread ----------------
__global__ void conv_silu(const float* __restrict__ ck, const float* __restrict__ cb)
{
    int idx = blockIdx.x * blockDim.x + threadIdx.x;   // < NTOK*DINNER/4
    if (idx >= NTOK * DINNER / 4) return;
    int dq = idx & (DINNER / 4 - 1);
    int bt = idx >> 9;
    int t  = bt & (SEQL - 1);
    int d  = dq * 4;

    float4 acc = *(const float4*)&cb[d];
#pragma unroll
    for (int w = 0; w < DCONV; w++) {
        int tt = t - (DCONV - 1) + w;
        if (tt >= 0) {
            float4 k = *(const float4*)&ck[w * DINNER + d];
            float4 v = *(const float4*)&g_xz[(size_t)(bt - (DCONV - 1) + w) * (2 * DINNER) + d];
            acc.x = fmaf(k.x, v.x, acc.x);
            acc.y = fmaf(k.y, v.y, acc.y);
            acc.z = fmaf(k.z, v.z, acc.z);
            acc.w = fmaf(k.w, v.w, acc.w);
        }
    }
    float4 u = make_float4(silu(acc.x), silu(acc.y), silu(acc.z), silu(acc.w));
    size_t o = (size_t)bt * DINNER + d;
    *(float4*)&g_u[o] = u;
    *(__half2*)&g_uh[o]     = __halves2half2(__float2half_rn(u.x), __float2half_rn(u.y));
    *(__half2*)&g_uh[o + 2] = __halves2half2(__float2half_rn(u.z), __float2half_rn(u.w));
}

// ---------------- chunked scan: phase 1 (chunk end-states, h0=0), smem B ----------------
__global__ __launch_bounds__(256) void scan_phase1(const float* __restrict__ A_log)
{
    __shared__ float sB[CLEN * DSTATE];    // 8 KB
    int tid = threadIdx.x;
    int ch = blockIdx.x * 16 + (tid >> 4);   // 0..4095
    int n = tid & 15;
    int c = blockIdx.y;
    int b = ch >> 11;
    int d = ch & (DINNER - 1);

    const float* xd = g_xdbl + (size_t)(b * SEQL + c * CLEN) * XDBL_LD;
    for (int i = tid; i < CLEN * DSTATE; i += 256)
        sB[i] = xd[(i >> 4) * XDBL_LD + DTRANK + (i & 15)];
    __syncthreads();

    float a = -expf(A_log[d * DSTATE + n]);
    float h = 0.f, sd = 0.f;

    const float* dptr = g_delta + (size_t)(b * SEQL + c * CLEN) * DINNER + d;
    const float* uptr = g_u     + (size_t)(b * SEQL + c * CLEN) * DINNER + d;

    for (int t = 0; t < CLEN; t++) {
        float delta = dptr[(size_t)t * DINNER];
        float uv    = uptr[(size_t)t * DINNER];
        float Bn    = sB[(t << 4) | n];
        h = __expf(delta * a) * h + delta * uv * Bn;
        sd += delta;
    }
    size_t idx = ((size_t)(b * DINNER + d) * DSTATE + n);
    g_hend[idx * NCHUNK + c] = h;
    if (n == 0) g_sumd[(size_t)(b * DINNER + d) * NCHUNK + c] = sd;
}

// ---------------- chunked scan: combine (sequential over 8 chunks) ----------------
__global__ void scan_combine(const float* __restrict__ A_log)
{
    int i = blockIdx.x * blockDim.x + threadIdx.x;     // < BATCH*DINNER*DSTATE
    if (i >= BATCH * DINNER * DSTATE) return;
    int n = i & 15;
    int d = (i >> 4) & (DINNER - 1);
    int bd = i >> 4;                                    // b*DINNER + d

    float a = -expf(A_log[d * DSTATE + n]);
    float H = 0.f;
#pragma unroll
    for (int c = 0; c < NCHUNK; c++) {
        g_h0[(size_t)i * NCHUNK + c] = H;
        float S = g_sumd[(size_t)bd * NCHUNK + c];
        H = __expf(a * S) * H + g_hend[(size_t)i * NCHUNK + c];
    }
}

// ---------------- chunked scan: phase 2 (y with true h0), smem B+C ----------------
__global__ __launch_bounds__(256) void scan_phase2(
    const float* __restrict__ A_log, const float* __restrict__ Dp)
{
    __shared__ float sBC[CLEN * 2 * DSTATE];   // 16 KB: [t][0..15]=B, [t][16..31]=C
    int tid = threadIdx.x;
    int ch = blockIdx.x * 16 + (tid >> 4);
    int n = tid & 15;
    int c = blockIdx.y;
    int b = ch >> 11;
    int d = ch & (DINNER - 1);

    const float* xd = g_xdbl + (size_t)(b * SEQL + c * CLEN) * XDBL_LD;
    for (int i = tid; i < CLEN * 2 * DSTATE; i += 256)
        sBC[i] = xd[(i >> 5) * XDBL_LD + DTRANK + (i & 31)];
    __syncthreads();

    float a = -expf(A_log[d * DSTATE + n]);
    float Dd = Dp[d];
    float h = g_h0[((size_t)(b * DINNER + d) * DSTATE + n) * NCHUNK + c];

    const float* dptr = g_delta + (size_t)(b * SEQL + c * CLEN) * DINNER + d;
    const float* uptr = g_u     + (size_t)(b * SEQL + c * CLEN) * DINNER + d;
    const float* zptr = g_zs    + (size_t)(b * SEQL + c * CLEN) * DINNER + d;
    __half* yh = g_yh + (size_t)(b * SEQL + c * CLEN) * DINNER + d;

    for (int t = 0; t < CLEN; t++) {
        float delta = dptr[(size_t)t * DINNER];
        float uv    = uptr[(size_t)t * DINNER];
        float Bn    = sBC[(t << 5) | n];
        float Cn    = sBC[(t << 5) | 16 | n];

        h = __expf(delta * a) * h + delta * uv * Bn;

        float p = h * Cn;
        p += __shfl_xor_sync(0xffffffffu, p, 8);
        p += __shfl_xor_sync(0xffffffffu, p, 4);
        p += __shfl_xor_sync(0xffffffffu, p, 2);
        p += __shfl_xor_sync(0xffffffffu, p, 1);

        if (n == 0) {
            float v = (p + uv * Dd) * zptr[(size_t)t * DINNER];
            yh[(size_t)t * DINNER] = __float2half_rn(v);
        }
    }
}

// ---------------- launch ----------------
extern "C" void kernel_launch(void* const* d_in, const int* in_sizes, int n_in,
                              void* d_out, int out_size)
{
    (void)in_sizes; (void)n_in; (void)out_size;
    const float* x     = (const float*)d_in[0];
    const float* W_in  = (const float*)d_in[1];
    const float* ck    = (const float*)d_in[2];
    const float* cb    = (const float*)d_in[3];
    const float* W_x   = (const float*)d_in[4];
    const float* W_dt  = (const float*)d_in[5];
    const float* b_dt  = (const float*)d_in[6];
    const float* W_out = (const float*)d_in[7];
    const float* A_log = (const float*)d_in[8];
    const float* Dp    = (const float*)d_in[9];
    float* out = (float*)d_out;

    cudaFuncSetAttribute((const void*)mma_gemm<0, 0>, cudaFuncAttributeMaxDynamicSharedMemorySize, MG_SMEM);
    cudaFuncSetAttribute((const void*)mma_gemm<1, 1>, cudaFuncAttributeMaxDynamicSharedMemorySize, MG_SMEM);
    cudaFuncSetAttribute((const void*)mma_gemm<3, 0>, cudaFuncAttributeMaxDynamicSharedMemorySize, MG_SMEM);

    float *p_xz, *p_delta, *p_osplit;
    cudaGetSymbolAddress((void**)&p_xz,    g_xz);
    cudaGetSymbolAddress((void**)&p_delta, g_delta);
    cudaGetSymbolAddress((void**)&p_osplit, g_osplit);
    __half *xh, *uh, *yh, *dth, *dtl;
    __half *wint, *wxt, *wdtt, *wot;
    cudaGetSymbolAddress((void**)&xh, g_xh);
    cudaGetSymbolAddress((void**)&uh, g_uh);
    cudaGetSymbolAddress((void**)&yh, g_yh);
    cudaGetSymbolAddress((void**)&dth, g_dth);   cudaGetSymbolAddress((void**)&dtl, g_dtl);
    cudaGetSymbolAddress((void**)&wint, g_wint);
    cudaGetSymbolAddress((void**)&wxt, g_wxt);
    cudaGetSymbolAddress((void**)&wdtt, g_wdtt);
    cudaGetSymbolAddress((void**)&wot, g_wot);

    // launch #1..#3: prep
    cvt_h<<<(NTOK * DMODEL / 4 + 255) / 256, 256>>>(x, xh, NTOK * DMODEL / 4);
    transpose_cvt<<<dim3(2 * DINNER / 32, DMODEL / 32), dim3(32, 8)>>>(W_in, DMODEL, 2 * DINNER, wint);
    transpose_cvt3<<<TB_OUT + TB_WX + TB_WDT, dim3(32, 8)>>>(W_out, W_x, W_dt, wot, wxt, wdtt);

    // launch #4: xz = x @ W_in : M=2048, N=4096, K=1024 (single-pass A); z -> silu -> g_zs
    mma_gemm<3, 0><<<dim3(32, 16, 1), 256, MG_SMEM>>>(
        xh, nullptr, DMODEL, wint, DMODEL, p_xz, 2 * DINNER, DMODEL, 1, nullptr, 0);

    // conv + silu -> u (fp32 + fp16 hi)
    conv_silu<<<(NTOK * DINNER / 4) / 256, 256>>>(ck, cb);

    // x_dbl = u @ W_x : M=2048, N=128(pad of 96), K=2048, split-K=8 -> buffers -> fused reduce
    mma_gemm<0, 0><<<dim3(1, 16, 8), 256, MG_SMEM>>>(
        uh, nullptr, DINNER, wxt, DINNER, p_osplit, XDBL_LD, DINNER, 8, nullptr, NTOK * XDBL_LD);
    reduce8_xdbl<<<(NTOK * XDBL_LD / 4 + 255) / 256, 256>>>(p_osplit);

    // delta = softplus(dt_lo @ W_dt + b_dt) : M=2048, N=2048, K=64 (2-pass A)
    mma_gemm<1, 1><<<dim3(16, 16, 1), 256, MG_SMEM>>>(
        dth, dtl, DTRANK, wdtt, DTRANK, p_delta, DINNER, DTRANK, 1, b_dt, 0);

    // chunked selective scan
    scan_phase1<<<dim3((BATCH * DINNER) / 16, NCHUNK), 256>>>(A_log);
    scan_combine<<<(BATCH * DINNER * DSTATE) / 256, 256>>>(A_log);
    scan_phase2<<<dim3((BATCH * DINNER) / 16, NCHUNK), 256>>>(A_log, Dp);

    // out = y @ W_out : M=2048, N=1024, K=2048, split-K=4 (single-pass A) -> reduce
    mma_gemm<0, 0><<<dim3(8, 16, 4), 256, MG_SMEM>>>(
        yh, nullptr, DINNER, wot, DINNER, p_osplit, DMODEL, DINNER, 4, nullptr, NTOK * DMODEL);
    reduce4<<<(NTOK * DMODEL / 4 + 255) / 256, 256>>>(p_osplit, out, NTOK * DMODEL / 4);
}

// round 13
// speedup vs baseline: 1.5061x; 1.0129x over previous
#include <cuda_runtime.h>
#include <cuda_fp16.h>
#include <math.h>
#include <stdint.h>

// ---------------- problem constants ----------------
#define BATCH   2
#define SEQL    1024
#define DMODEL  1024
#define DINNER  2048
#define DSTATE  16
#define DCONV   4
#define DTRANK  64
#define NTOK    (BATCH * SEQL)          // 2048
#define XDBL_LD 128                     // padded (dt 0..63 | B 64..79 | C 80..95 | pad)
#define NCHUNK  8
#define CLEN    (SEQL / NCHUNK)         // 128

// ---------------- PTX helpers (portable: sm_80-era features only) ----------------
__device__ __forceinline__ uint32_t smem_to_u32(const void* p) {
    uint32_t a;
    asm("{ .reg .u64 t; cvta.to.shared.u64 t, %1; cvt.u32.u64 %0, t; }" : "=r"(a) : "l"(p));
    return a;
}
__device__ __forceinline__ void cpasync16(uint32_t s, const void* g) {
    asm volatile("cp.async.cg.shared.global [%0], [%1], 16;" :: "r"(s), "l"(g));
}
#define CP_COMMIT()  asm volatile("cp.async.commit_group;" ::: "memory")
#define CP_WAIT0()   asm volatile("cp.async.wait_group 0;" ::: "memory")
#define CP_WAIT1()   asm volatile("cp.async.wait_group 1;" ::: "memory")
#define LDSM4(r, addr) \
    asm volatile("ldmatrix.sync.aligned.m8n8.x4.shared.b16 {%0,%1,%2,%3}, [%4];" \
        : "=r"((r)[0]), "=r"((r)[1]), "=r"((r)[2]), "=r"((r)[3]) : "r"(addr))

__device__ __forceinline__ void mma16816(float* d, const uint32_t* a, const uint32_t* b) {
    asm volatile(
        "mma.sync.aligned.m16n8k16.row.col.f32.f16.f16.f32 "
        "{%0,%1,%2,%3}, {%4,%5,%6,%7}, {%8,%9}, {%0,%1,%2,%3};"
        : "+f"(d[0]), "+f"(d[1]), "+f"(d[2]), "+f"(d[3])
        : "r"(a[0]), "r"(a[1]), "r"(a[2]), "r"(a[3]), "r"(b[0]), "r"(b[1]));
}

// swizzled byte offset of 16B chunk c (0..7) in row r (row = 128 bytes = 8 chunks)
__device__ __forceinline__ uint32_t sw_off(int r, int c) {
    return (uint32_t)(r * 128 + ((c ^ (r & 7)) << 4));
}
__device__ __forceinline__ float silu(float v) { return v / (1.f + __expf(-v)); }

// ---------------- scratch (device globals) ----------------
__device__ float g_xz[(size_t)NTOK * 2 * DINNER];     // u_raw (z half unused)
__device__ float g_u[(size_t)NTOK * DINNER];          // fp32 u for the scan
__device__ float g_zs[(size_t)NTOK * DINNER];
__device__ float g_xdbl[(size_t)NTOK * XDBL_LD];
__device__ float g_delta[(size_t)NTOK * DINNER];
__device__ float g_osplit[(size_t)4 * NTOK * DMODEL]; // split-K buffers (xdbl: 8x2048x128; out: 4x2048x1024)
// chunked-scan state
__device__ float g_hend[(size_t)BATCH * DINNER * DSTATE * NCHUNK];
__device__ float g_sumd[(size_t)BATCH * DINNER * NCHUNK];

// A-side fp16
__device__ __half g_xh[(size_t)NTOK * DMODEL];                       // single-pass
__device__ __half g_uh[(size_t)NTOK * DINNER];                       // single-pass
__device__ __half g_yh[(size_t)NTOK * DINNER];                       // single-pass
__device__ __half g_dth[(size_t)NTOK * DTRANK],  g_dtl[(size_t)NTOK * DTRANK];  // 2-pass
// B-side: transposed single fp16 weights: [N][K] row-major (K contiguous)
__device__ __half g_wint[(size_t)2 * DINNER * DMODEL];
__device__ __half g_wxt[(size_t)XDBL_LD * DINNER];
__device__ __half g_wdtt[(size_t)DINNER * DTRANK];
__device__ __half g_wot[(size_t)DMODEL * DINNER];

// ---------------- mma.sync fp16 GEMM, K-tile 64 ----------------
// C[M,N] = (Ah [+ Al])[M,K] @ B[K,N], B given transposed [N][K], fp32 accum.
// TWO=0: 3-stage pipeline, 32KB stages, 1 barrier/iter (Ah 0..16K, B 16..32K).
// TWO=1: 2-stage pipeline, 48KB stages (Ah 0..16K, Al 16..32K, B 32..48K).
// EPI 0: store (+zstride per blockIdx.z), 1: softplus(acc+bias),
// EPI 3: store u-half raw; z-half -> silu to g_zs
#define MG_SMEM 98304
template <int EPI, int TWO>
__global__ __launch_bounds__(256, 2) void mma_gemm(
    const __half* __restrict__ Ah, const __half* __restrict__ Al, int lda,
    const __half* __restrict__ B, int ldb,
    float* __restrict__ C, int ldc, int K, int KS, const float* __restrict__ bias,
    int zstride)
{
    extern __shared__ char smem[];
    uint32_t sb = smem_to_u32(smem);
    const uint32_t SSZ   = TWO ? 49152u : 32768u;
    const uint32_t B_OFF = TWO ? 32768u : 16384u;
    const int NST = TWO ? 2 : 3;
    const int tid = threadIdx.x, lane = tid & 31, wid = tid >> 5;
    const int wm = wid & 3, wn = wid >> 2;          // warp tile: rows wm*32, cols wn*64
    const int row0 = blockIdx.y * 128, col0 = blockIdx.x * 128;
    const int kper = K / KS;
    const int kbeg = blockIdx.z * kper;
    const int kn = kper >> 6;                        // 64-wide k tiles

    float acc[2][8][4];
#pragma unroll
    for (int i = 0; i < 2; i++)
#pragma unroll
        for (int j = 0; j < 8; j++)
#pragma unroll
            for (int r = 0; r < 4; r++) acc[i][j][r] = 0.f;

    auto load_stage = [&](int s, int k0) {
        uint32_t base = sb + s * SSZ;
#pragma unroll
        for (int j = 0; j < 4; j++) {
            int idx = tid + j * 256;                 // 0..1023
            int r = idx >> 3, c = idx & 7;
            uint32_t so = sw_off(r, c);
            size_t ao = (size_t)(row0 + r) * lda + k0 + c * 8;
            size_t bo = (size_t)(col0 + r) * ldb + k0 + c * 8;
            cpasync16(base + so,           Ah + ao);
            if (TWO) cpasync16(base + 16384 + so, Al + ao);
            cpasync16(base + B_OFF + so,   B + bo);
        }
        CP_COMMIT();
    };

    load_stage(0, kbeg);
    if (kn > 1) load_stage(1, kbeg + 64);

    const int a_row = wm * 32 + ((lane >> 3) & 1) * 8 + (lane & 7);   // + mi*16
    const int b_row = wn * 64 + (lane >> 4) * 8 + (lane & 7);         // + j*16

    for (int it = 0; it < kn; it++) {
        if (it + 1 < kn) CP_WAIT1(); else CP_WAIT0();
        __syncthreads();
        uint32_t base = sb + (it % NST) * SSZ;
#pragma unroll
        for (int kk = 0; kk < 4; kk++) {
            uint32_t ah[2][4], al[2][4], bb[8][2];
#pragma unroll
            for (int mi = 0; mi < 2; mi++) {
                int r = a_row + mi * 16;
                int c = kk * 2 + (lane >> 4);
                uint32_t so = sw_off(r, c);
                LDSM4(ah[mi], base + so);
                if (TWO) LDSM4(al[mi], base + 16384 + so);
            }
#pragma unroll
            for (int j = 0; j < 4; j++) {
                int r = b_row + j * 16;
                int c = kk * 2 + ((lane >> 3) & 1);
                uint32_t so = sw_off(r, c);
                uint32_t t[4];
                LDSM4(t, base + B_OFF + so);
                bb[2 * j][0] = t[0]; bb[2 * j][1] = t[1];
                bb[2 * j + 1][0] = t[2]; bb[2 * j + 1][1] = t[3];
            }
#pragma unroll
            for (int mi = 0; mi < 2; mi++)
#pragma unroll
                for (int nj = 0; nj < 8; nj++) {
                    mma16816(acc[mi][nj], ah[mi], bb[nj]);
                    if (TWO) mma16816(acc[mi][nj], al[mi], bb[nj]);
                }
        }
        if (TWO) __syncthreads();   // 2-stage: protect stage (it+2)%2 == it%2
        if (it + 2 < kn) load_stage((it + 2) % NST, kbeg + (it + 2) * 64);
        // TWO=0 (3-stage): load target (it+2)%3 differs from it%3 (current readers)
        // and its last readers (iter it-1) all passed the barrier above. Safe.
    }

    if (EPI == 0) C += (size_t)blockIdx.z * zstride;

#pragma unroll
    for (int mi = 0; mi < 2; mi++) {
        int row = row0 + wm * 32 + mi * 16 + (lane >> 2);
#pragma unroll
        for (int nj = 0; nj < 8; nj++) {
            int col = col0 + wn * 64 + nj * 8 + (lane & 3) * 2;
            float* a = acc[mi][nj];
            if (EPI == 0) {
                *(float2*)&C[(size_t)row * ldc + col]       = make_float2(a[0], a[1]);
                *(float2*)&C[(size_t)(row + 8) * ldc + col] = make_float2(a[2], a[3]);
            } else if (EPI == 1) {
                float b0 = bias[col], b1 = bias[col + 1];
                float v0 = a[0] + b0, v1 = a[1] + b1, v2 = a[2] + b0, v3 = a[3] + b1;
                v0 = (v0 > 20.f) ? v0 : __logf(1.f + __expf(v0));
                v1 = (v1 > 20.f) ? v1 : __logf(1.f + __expf(v1));
                v2 = (v2 > 20.f) ? v2 : __logf(1.f + __expf(v2));
                v3 = (v3 > 20.f) ? v3 : __logf(1.f + __expf(v3));
                *(float2*)&C[(size_t)row * ldc + col]       = make_float2(v0, v1);
                *(float2*)&C[(size_t)(row + 8) * ldc + col] = make_float2(v2, v3);
            } else {  // EPI == 3: xz epilogue. cols < DINNER raw; cols >= DINNER -> silu -> g_zs
                if (col < DINNER) {
                    *(float2*)&C[(size_t)row * ldc + col]       = make_float2(a[0], a[1]);
                    *(float2*)&C[(size_t)(row + 8) * ldc + col] = make_float2(a[2], a[3]);
                } else {
                    int zc = col - DINNER;
                    *(float2*)&g_zs[(size_t)row * DINNER + zc]       = make_float2(silu(a[0]), silu(a[1]));
                    *(float2*)&g_zs[(size_t)(row + 8) * DINNER + zc] = make_float2(silu(a[2]), silu(a[3]));
                }
            }
        }
    }
}

// ---------------- reduce 4 split-K buffers into out ----------------
__global__ void reduce4(const float* __restrict__ src, float* __restrict__ dst, int n4) {
    int i = blockIdx.x * blockDim.x + threadIdx.x;
    if (i >= n4) return;
    const float4* s = (const float4*)src;
    float4 a = s[i], b = s[i + n4], c = s[i + 2 * n4], d = s[i + 3 * n4];
    float4 r = make_float4(a.x + b.x + c.x + d.x, a.y + b.y + c.y + d.y,
                           a.z + b.z + c.z + d.z, a.w + b.w + c.w + d.w);
    ((float4*)dst)[i] = r;
}

// ---------------- reduce 8 split-K xdbl buffers -> g_xdbl + dt hi/lo split ----------------
__global__ void reduce8_xdbl(const float* __restrict__ src) {
    int i = blockIdx.x * blockDim.x + threadIdx.x;   // < NTOK*XDBL_LD/4
    const int n4 = NTOK * XDBL_LD / 4;
    if (i >= n4) return;
    const float4* s = (const float4*)src;
    float4 r = s[i];
#pragma unroll
    for (int k = 1; k < 8; k++) {
        float4 v = s[i + k * n4];
        r.x += v.x; r.y += v.y; r.z += v.z; r.w += v.w;
    }
    ((float4*)g_xdbl)[i] = r;
    int t  = i >> 5;          // row (32 float4 chunks per 128-col row)
    int cq = i & 31;
    if (cq < DTRANK / 4) {    // dt region
        int c = cq * 4;
        __half h0 = __float2half_rn(r.x), h1 = __float2half_rn(r.y);
        __half h2 = __float2half_rn(r.z), h3 = __float2half_rn(r.w);
        size_t o = (size_t)t * DTRANK + c;
        *(__half2*)&g_dth[o]     = __halves2half2(h0, h1);
        *(__half2*)&g_dth[o + 2] = __halves2half2(h2, h3);
        *(__half2*)&g_dtl[o]     = __halves2half2(__float2half_rn(r.x - __half2float(h0)),
                                                  __float2half_rn(r.y - __half2float(h1)));
        *(__half2*)&g_dtl[o + 2] = __halves2half2(__float2half_rn(r.z - __half2float(h2)),
                                                  __float2half_rn(r.w - __half2float(h3)));
    }
}

// ---------------- transpose body (shared) ----------------
__device__ __forceinline__ void trans_body(const float* __restrict__ W, int K, int N,
                                           __half* __restrict__ T, int bx, int by,
                                           float t[32][33])
{
    int tx = threadIdx.x, ty0 = threadIdx.y;
#pragma unroll
    for (int s = 0; s < 4; s++) {
        int ty = ty0 + s * 8;
        int col = bx * 32 + tx;          // n
        int row = by * 32 + ty;          // k
        t[ty][tx] = (col < N) ? W[(size_t)row * N + col] : 0.f;
    }
    __syncthreads();
#pragma unroll
    for (int s = 0; s < 4; s++) {
        int ty = ty0 + s * 8;
        int n = bx * 32 + ty;
        int k = by * 32 + tx;
        T[(size_t)n * K + k] = __float2half_rn(t[tx][ty]);
    }
}

// ---------------- ONE prep kernel: cvt_h(x) + all 4 weight transposes ----------------
// regions (blocks): [0,2048) cvt x | [2048,6144) W_in | [6144,8192) W_out |
//                   [8192,8448) W_x | [8448,8576) W_dt
__global__ void prep_all(const float* __restrict__ x,
                         const float* __restrict__ Win, const float* __restrict__ Wout,
                         const float* __restrict__ Wx,  const float* __restrict__ Wdt)
{
    __shared__ float t[32][33];
    int bid = blockIdx.x;
    if (bid < 2048) {
        int i = bid * 256 + threadIdx.y * 32 + threadIdx.x;   // < 524288 = NTOK*DMODEL/4
        float4 v = ((const float4*)x)[i];
        ((__half2*)g_xh)[i * 2]     = __halves2half2(__float2half_rn(v.x), __float2half_rn(v.y));
        ((__half2*)g_xh)[i * 2 + 1] = __halves2half2(__float2half_rn(v.z), __float2half_rn(v.w));
        return;
    }
    bid -= 2048;
    if (bid < 4096) { trans_body(Win, DMODEL, 2 * DINNER, g_wint, bid & 127, bid >> 7, t); return; }
    bid -= 4096;
    if (bid < 2048) { trans_body(Wout, DINNER, DMODEL, g_wot, bid & 31, bid >> 5, t); return; }
    bid -= 2048;
    if (bid < 256)  { trans_body(Wx, DINNER, DTRANK + 2 * DSTATE, g_wxt, bid & 3, bid >> 2, t); return; }
    bid -= 256;
    trans_body(Wdt, DTRANK, DINNER, g_wdtt, bid & 63, bid >> 6, t);
}

// ---------------- conv + SiLU -> fp32 u + fp16 hi, 4 channels/thread ----------------
__global__ void conv_silu(const float* __restrict__ ck, const float* __restrict__ cb)
{
    int idx = blockIdx.x * blockDim.x + threadIdx.x;   // < NTOK*DINNER/4
    if (idx >= NTOK * DINNER / 4) return;
    int dq = idx & (DINNER / 4 - 1);
    int bt = idx >> 9;
    int t  = bt & (SEQL - 1);
    int d  = dq * 4;

    float4 acc = *(const float4*)&cb[d];
#pragma unroll
    for (int w = 0; w < DCONV; w++) {
        int tt = t - (DCONV - 1) + w;
        if (tt >= 0) {
            float4 k = *(const float4*)&ck[w * DINNER + d];
            float4 v = *(const float4*)&g_xz[(size_t)(bt - (DCONV - 1) + w) * (2 * DINNER) + d];
            acc.x = fmaf(k.x, v.x, acc.x);
            acc.y = fmaf(k.y, v.y, acc.y);
            acc.z = fmaf(k.z, v.z, acc.z);
            acc.w = fmaf(k.w, v.w, acc.w);
        }
    }
    float4 u = make_float4(silu(acc.x), silu(acc.y), silu(acc.z), silu(acc.w));
    size_t o = (size_t)bt * DINNER + d;
    *(float4*)&g_u[o] = u;
    *(__half2*)&g_uh[o]     = __halves2half2(__float2half_rn(u.x), __float2half_rn(u.y));
    *(__half2*)&g_uh[o + 2] = __halves2half2(__float2half_rn(u.z), __float2half_rn(u.w));
}

// ---------------- chunked scan: phase 1 (chunk end-states, h0=0), smem B ----------------
__global__ __launch_bounds__(256) void scan_phase1(const float* __restrict__ A_log)
{
    __shared__ float sB[CLEN * DSTATE];    // 8 KB
    int tid = threadIdx.x;
    int ch = blockIdx.x * 16 + (tid >> 4);   // 0..4095
    int n = tid & 15;
    int c = blockIdx.y;
    int b = ch >> 11;
    int d = ch & (DINNER - 1);

    const float* xd = g_xdbl + (size_t)(b * SEQL + c * CLEN) * XDBL_LD;
    for (int i = tid; i < CLEN * DSTATE; i += 256)
        sB[i] = xd[(i >> 4) * XDBL_LD + DTRANK + (i & 15)];
    __syncthreads();

    float a = -expf(A_log[d * DSTATE + n]);
    float h = 0.f, sd = 0.f;

    const float* dptr = g_delta + (size_t)(b * SEQL + c * CLEN) * DINNER + d;
    const float* uptr = g_u     + (size_t)(b * SEQL + c * CLEN) * DINNER + d;

    for (int t = 0; t < CLEN; t++) {
        float delta = dptr[(size_t)t * DINNER];
        float uv    = uptr[(size_t)t * DINNER];
        float Bn    = sB[(t << 4) | n];
        h = __expf(delta * a) * h + delta * uv * Bn;
        sd += delta;
    }
    size_t idx = ((size_t)(b * DINNER + d) * DSTATE + n);
    g_hend[idx * NCHUNK + c] = h;
    if (n == 0) g_sumd[(size_t)(b * DINNER + d) * NCHUNK + c] = sd;
}

// ---------------- chunked scan: phase 2 (inline combine + y), smem B+C ----------------
__global__ __launch_bounds__(256) void scan_phase2(
    const float* __restrict__ A_log, const float* __restrict__ Dp)
{
    __shared__ float sBC[CLEN * 2 * DSTATE];   // 16 KB: [t][0..15]=B, [t][16..31]=C
    int tid = threadIdx.x;
    int ch = blockIdx.x * 16 + (tid >> 4);
    int n = tid & 15;
    int c = blockIdx.y;
    int b = ch >> 11;
    int d = ch & (DINNER - 1);

    const float* xd = g_xdbl + (size_t)(b * SEQL + c * CLEN) * XDBL_LD;
    for (int i = tid; i < CLEN * 2 * DSTATE; i += 256)
        sBC[i] = xd[(i >> 5) * XDBL_LD + DTRANK + (i & 31)];
    __syncthreads();

    float a = -expf(A_log[d * DSTATE + n]);
    float Dd = Dp[d];

    // inline combine: h0 for this chunk = fold of previous chunks
    float h = 0.f;
    {
        size_t bi = ((size_t)(b * DINNER + d) * DSTATE + n) * NCHUNK;
        size_t bs = (size_t)(b * DINNER + d) * NCHUNK;
        for (int cc = 0; cc < c; cc++)
            h = __expf(a * g_sumd[bs + cc]) * h + g_hend[bi + cc];
    }

    const float* dptr = g_delta + (size_t)(b * SEQL + c * CLEN) * DINNER + d;
    const float* uptr = g_u     + (size_t)(b * SEQL + c * CLEN) * DINNER + d;
    const float* zptr = g_zs    + (size_t)(b * SEQL + c * CLEN) * DINNER + d;
    __half* yh = g_yh + (size_t)(b * SEQL + c * CLEN) * DINNER + d;

    for (int t = 0; t < CLEN; t++) {
        float delta = dptr[(size_t)t * DINNER];
        float uv    = uptr[(size_t)t * DINNER];
        float Bn    = sBC[(t << 5) | n];
        float Cn    = sBC[(t << 5) | 16 | n];

        h = __expf(delta * a) * h + delta * uv * Bn;

        float p = h * Cn;
        p += __shfl_xor_sync(0xffffffffu, p, 8);
        p += __shfl_xor_sync(0xffffffffu, p, 4);
        p += __shfl_xor_sync(0xffffffffu, p, 2);
        p += __shfl_xor_sync(0xffffffffu, p, 1);

        if (n == 0) {
            float v = (p + uv * Dd) * zptr[(size_t)t * DINNER];
            yh[(size_t)t * DINNER] = __float2half_rn(v);
        }
    }
}

// ---------------- launch ----------------
extern "C" void kernel_launch(void* const* d_in, const int* in_sizes, int n_in,
                              void* d_out, int out_size)
{
    (void)in_sizes; (void)n_in; (void)out_size;
    const float* x     = (const float*)d_in[0];
    const float* W_in  = (const float*)d_in[1];
    const float* ck    = (const float*)d_in[2];
    const float* cb    = (const float*)d_in[3];
    const float* W_x   = (const float*)d_in[4];
    const float* W_dt  = (const float*)d_in[5];
    const float* b_dt  = (const float*)d_in[6];
    const float* W_out = (const float*)d_in[7];
    const float* A_log = (const float*)d_in[8];
    const float* Dp    = (const float*)d_in[9];
    float* out = (float*)d_out;

    cudaFuncSetAttribute((const void*)mma_gemm<0, 0>, cudaFuncAttributeMaxDynamicSharedMemorySize, MG_SMEM);
    cudaFuncSetAttribute((const void*)mma_gemm<1, 1>, cudaFuncAttributeMaxDynamicSharedMemorySize, MG_SMEM);
    cudaFuncSetAttribute((const void*)mma_gemm<3, 0>, cudaFuncAttributeMaxDynamicSharedMemorySize, MG_SMEM);

    float *p_xz, *p_delta, *p_osplit;
    cudaGetSymbolAddress((void**)&p_xz,    g_xz);
    cudaGetSymbolAddress((void**)&p_delta, g_delta);
    cudaGetSymbolAddress((void**)&p_osplit, g_osplit);
    __half *xh, *uh, *yh, *dth, *dtl;
    __half *wint, *wxt, *wdtt, *wot;
    cudaGetSymbolAddress((void**)&xh, g_xh);
    cudaGetSymbolAddress((void**)&uh, g_uh);
    cudaGetSymbolAddress((void**)&yh, g_yh);
    cudaGetSymbolAddress((void**)&dth, g_dth);   cudaGetSymbolAddress((void**)&dtl, g_dtl);
    cudaGetSymbolAddress((void**)&wint, g_wint);
    cudaGetSymbolAddress((void**)&wxt, g_wxt);
    cudaGetSymbolAddress((void**)&wdtt, g_wdtt);
    cudaGetSymbolAddress((void**)&wot, g_wot);

    // launch #1: ALL prep (cvt x + 4 weight transposes)
    prep_all<<<8576, dim3(32, 8)>>>(x, W_in, W_out, W_x, W_dt);
    // pad launches so GEMM1 stays in ncu slot #4 (two tiny no-op-ish reduces? no —
    // keep profile slot stable by issuing prep as 3 separate waves is wasteful; accept slot change)

    // launch #2: xz = x @ W_in : M=2048, N=4096, K=1024 (single-pass A); z -> silu -> g_zs
    mma_gemm<3, 0><<<dim3(32, 16, 1), 256, MG_SMEM>>>(
        xh, nullptr, DMODEL, wint, DMODEL, p_xz, 2 * DINNER, DMODEL, 1, nullptr, 0);

    // conv + silu -> u (fp32 + fp16 hi)
    conv_silu<<<(NTOK * DINNER / 4) / 256, 256>>>(ck, cb);

    // x_dbl = u @ W_x : M=2048, N=128(pad of 96), K=2048, split-K=8 -> buffers -> fused reduce
    mma_gemm<0, 0><<<dim3(1, 16, 8), 256, MG_SMEM>>>(
        uh, nullptr, DINNER, wxt, DINNER, p_osplit, XDBL_LD, DINNER, 8, nullptr, NTOK * XDBL_LD);
    reduce8_xdbl<<<(NTOK * XDBL_LD / 4 + 255) / 256, 256>>>(p_osplit);

    // delta = softplus(dt_lo @ W_dt + b_dt) : M=2048, N=2048, K=64 (2-pass A)
    mma_gemm<1, 1><<<dim3(16, 16, 1), 256, MG_SMEM>>>(
        dth, dtl, DTRANK, wdtt, DTRANK, p_delta, DINNER, DTRANK, 1, b_dt, 0);

    // chunked selective scan (combine folded into phase 2)
    scan_phase1<<<dim3((BATCH * DINNER) / 16, NCHUNK), 256>>>(A_log);
    scan_phase2<<<dim3((BATCH * DINNER) / 16, NCHUNK), 256>>>(A_log, Dp);

    // out = y @ W_out : M=2048, N=1024, K=2048, split-K=4 (single-pass A) -> reduce
    mma_gemm<0, 0><<<dim3(8, 16, 4), 256, MG_SMEM>>>(
        yh, nullptr, DINNER, wot, DINNER, p_osplit, DMODEL, DINNER, 4, nullptr, NTOK * DMODEL);
    reduce4<<<(NTOK * DMODEL / 4 + 255) / 256, 256>>>(p_osplit, out, NTOK * DMODEL / 4);
}

// round 14
// speedup vs baseline: 1.5406x; 1.0229x over previous
#include <cuda_runtime.h>
#include <cuda_fp16.h>
#include <math.h>
#include <stdint.h>

// ---------------- problem constants ----------------
#define BATCH   2
#define SEQL    1024
#define DMODEL  1024
#define DINNER  2048
#define DSTATE  16
#define DCONV   4
#define DTRANK  64
#define NTOK    (BATCH * SEQL)          // 2048
#define XDBL_LD 128                     // padded (dt 0..63 | B 64..79 | C 80..95 | pad)
#define NCHUNK  8
#define CLEN    (SEQL / NCHUNK)         // 128

// ---------------- PTX helpers (portable: sm_80-era features only) ----------------
__device__ __forceinline__ uint32_t smem_to_u32(const void* p) {
    uint32_t a;
    asm("{ .reg .u64 t; cvta.to.shared.u64 t, %1; cvt.u32.u64 %0, t; }" : "=r"(a) : "l"(p));
    return a;
}
__device__ __forceinline__ void cpasync16(uint32_t s, const void* g) {
    asm volatile("cp.async.cg.shared.global [%0], [%1], 16;" :: "r"(s), "l"(g));
}
#define CP_COMMIT()  asm volatile("cp.async.commit_group;" ::: "memory")
#define CP_WAIT0()   asm volatile("cp.async.wait_group 0;" ::: "memory")
#define CP_WAIT1()   asm volatile("cp.async.wait_group 1;" ::: "memory")
#define LDSM4(r, addr) \
    asm volatile("ldmatrix.sync.aligned.m8n8.x4.shared.b16 {%0,%1,%2,%3}, [%4];" \
        : "=r"((r)[0]), "=r"((r)[1]), "=r"((r)[2]), "=r"((r)[3]) : "r"(addr))

__device__ __forceinline__ void mma16816(float* d, const uint32_t* a, const uint32_t* b) {
    asm volatile(
        "mma.sync.aligned.m16n8k16.row.col.f32.f16.f16.f32 "
        "{%0,%1,%2,%3}, {%4,%5,%6,%7}, {%8,%9}, {%0,%1,%2,%3};"
        : "+f"(d[0]), "+f"(d[1]), "+f"(d[2]), "+f"(d[3])
        : "r"(a[0]), "r"(a[1]), "r"(a[2]), "r"(a[3]), "r"(b[0]), "r"(b[1]));
}

// swizzled byte offset of 16B chunk c (0..7) in row r (row = 128 bytes = 8 chunks)
__device__ __forceinline__ uint32_t sw_off(int r, int c) {
    return (uint32_t)(r * 128 + ((c ^ (r & 7)) << 4));
}
__device__ __forceinline__ float silu(float v) { return v / (1.f + __expf(-v)); }

// ---------------- scratch (device globals) ----------------
__device__ __half g_uraw[(size_t)NTOK * DINNER];      // pre-conv u (fp16)
__device__ __half g_zsh[(size_t)NTOK * DINNER];       // silu(z) fp16
__device__ __half g_dh[(size_t)NTOK * DINNER];        // delta fp16
__device__ float  g_xdbl[(size_t)NTOK * XDBL_LD];     // fp32 (B/C for scan)
__device__ float  g_osplit[(size_t)4 * NTOK * DMODEL]; // split-K buffers
// chunked-scan state
__device__ float g_hend[(size_t)BATCH * DINNER * DSTATE * NCHUNK];
__device__ float g_sumd[(size_t)BATCH * DINNER * NCHUNK];

// A-side fp16 (all single-pass now)
__device__ __half g_xh[(size_t)NTOK * DMODEL];
__device__ __half g_uh[(size_t)NTOK * DINNER];        // silu(conv(u_raw)) fp16
__device__ __half g_yh[(size_t)NTOK * DINNER];
__device__ __half g_dth[(size_t)NTOK * DTRANK];
// B-side: transposed single fp16 weights: [N][K] row-major (K contiguous)
__device__ __half g_wint[(size_t)2 * DINNER * DMODEL];
__device__ __half g_wxt[(size_t)XDBL_LD * DINNER];
__device__ __half g_wdtt[(size_t)DINNER * DTRANK];
__device__ __half g_wot[(size_t)DMODEL * DINNER];

// ---------------- mma.sync fp16 GEMM, K-tile 64 ----------------
// C[M,N] = Ah[M,K] @ B[K,N], B given transposed [N][K], fp32 accum. Single-pass A.
// 3-stage pipeline, 32KB stages, 1 barrier/iter (Ah 0..16K, B 16..32K).
// EPI 0: store fp32 to C (+zstride per blockIdx.z)
// EPI 1: softplus(acc+bias) -> fp16 g_dh
// EPI 3: u-half -> fp16 g_uraw; z-half -> silu -> fp16 g_zsh
#define MG_SMEM 98304
template <int EPI>
__global__ __launch_bounds__(256, 2) void mma_gemm(
    const __half* __restrict__ Ah, int lda,
    const __half* __restrict__ B, int ldb,
    float* __restrict__ C, int ldc, int K, int KS, const float* __restrict__ bias,
    int zstride)
{
    extern __shared__ char smem[];
    uint32_t sb = smem_to_u32(smem);
    const uint32_t SSZ = 32768u, B_OFF = 16384u;
    const int NST = 3;
    const int tid = threadIdx.x, lane = tid & 31, wid = tid >> 5;
    const int wm = wid & 3, wn = wid >> 2;          // warp tile: rows wm*32, cols wn*64
    const int row0 = blockIdx.y * 128, col0 = blockIdx.x * 128;
    const int kper = K / KS;
    const int kbeg = blockIdx.z * kper;
    const int kn = kper >> 6;                        // 64-wide k tiles

    float acc[2][8][4];
#pragma unroll
    for (int i = 0; i < 2; i++)
#pragma unroll
        for (int j = 0; j < 8; j++)
#pragma unroll
            for (int r = 0; r < 4; r++) acc[i][j][r] = 0.f;

    auto load_stage = [&](int s, int k0) {
        uint32_t base = sb + s * SSZ;
#pragma unroll
        for (int j = 0; j < 4; j++) {
            int idx = tid + j * 256;                 // 0..1023
            int r = idx >> 3, c = idx & 7;
            uint32_t so = sw_off(r, c);
            cpasync16(base + so,         Ah + (size_t)(row0 + r) * lda + k0 + c * 8);
            cpasync16(base + B_OFF + so, B  + (size_t)(col0 + r) * ldb + k0 + c * 8);
        }
        CP_COMMIT();
    };

    load_stage(0, kbeg);
    if (kn > 1) load_stage(1, kbeg + 64);

    const int a_row = wm * 32 + ((lane >> 3) & 1) * 8 + (lane & 7);   // + mi*16
    const int b_row = wn * 64 + (lane >> 4) * 8 + (lane & 7);         // + j*16

    for (int it = 0; it < kn; it++) {
        if (it + 1 < kn) CP_WAIT1(); else CP_WAIT0();
        __syncthreads();
        uint32_t base = sb + (it % NST) * SSZ;
#pragma unroll
        for (int kk = 0; kk < 4; kk++) {
            uint32_t ah[2][4], bb[8][2];
#pragma unroll
            for (int mi = 0; mi < 2; mi++) {
                int r = a_row + mi * 16;
                int c = kk * 2 + (lane >> 4);
                LDSM4(ah[mi], base + sw_off(r, c));
            }
#pragma unroll
            for (int j = 0; j < 4; j++) {
                int r = b_row + j * 16;
                int c = kk * 2 + ((lane >> 3) & 1);
                uint32_t t[4];
                LDSM4(t, base + B_OFF + sw_off(r, c));
                bb[2 * j][0] = t[0]; bb[2 * j][1] = t[1];
                bb[2 * j + 1][0] = t[2]; bb[2 * j + 1][1] = t[3];
            }
#pragma unroll
            for (int mi = 0; mi < 2; mi++)
#pragma unroll
                for (int nj = 0; nj < 8; nj++)
                    mma16816(acc[mi][nj], ah[mi], bb[nj]);
        }
        if (it + 2 < kn) load_stage((it + 2) % NST, kbeg + (it + 2) * 64);
        // 3-stage: load target (it+2)%3 != it%3 (current readers) and its last
        // readers (iter it-1) passed the barrier above. Safe with one barrier.
    }

    if (EPI == 0) C += (size_t)blockIdx.z * zstride;

#pragma unroll
    for (int mi = 0; mi < 2; mi++) {
        int row = row0 + wm * 32 + mi * 16 + (lane >> 2);
#pragma unroll
        for (int nj = 0; nj < 8; nj++) {
            int col = col0 + wn * 64 + nj * 8 + (lane & 3) * 2;
            float* a = acc[mi][nj];
            if (EPI == 0) {
                *(float2*)&C[(size_t)row * ldc + col]       = make_float2(a[0], a[1]);
                *(float2*)&C[(size_t)(row + 8) * ldc + col] = make_float2(a[2], a[3]);
            } else if (EPI == 1) {
                float b0 = bias[col], b1 = bias[col + 1];
                float v0 = a[0] + b0, v1 = a[1] + b1, v2 = a[2] + b0, v3 = a[3] + b1;
                v0 = (v0 > 20.f) ? v0 : __logf(1.f + __expf(v0));
                v1 = (v1 > 20.f) ? v1 : __logf(1.f + __expf(v1));
                v2 = (v2 > 20.f) ? v2 : __logf(1.f + __expf(v2));
                v3 = (v3 > 20.f) ? v3 : __logf(1.f + __expf(v3));
                *(__half2*)&g_dh[(size_t)row * DINNER + col] =
                    __halves2half2(__float2half_rn(v0), __float2half_rn(v1));
                *(__half2*)&g_dh[(size_t)(row + 8) * DINNER + col] =
                    __halves2half2(__float2half_rn(v2), __float2half_rn(v3));
            } else {  // EPI == 3
                if (col < DINNER) {
                    *(__half2*)&g_uraw[(size_t)row * DINNER + col] =
                        __halves2half2(__float2half_rn(a[0]), __float2half_rn(a[1]));
                    *(__half2*)&g_uraw[(size_t)(row + 8) * DINNER + col] =
                        __halves2half2(__float2half_rn(a[2]), __float2half_rn(a[3]));
                } else {
                    int zc = col - DINNER;
                    *(__half2*)&g_zsh[(size_t)row * DINNER + zc] =
                        __halves2half2(__float2half_rn(silu(a[0])), __float2half_rn(silu(a[1])));
                    *(__half2*)&g_zsh[(size_t)(row + 8) * DINNER + zc] =
                        __halves2half2(__float2half_rn(silu(a[2])), __float2half_rn(silu(a[3])));
                }
            }
        }
    }
}

// ---------------- reduce 4 split-K buffers into out ----------------
__global__ void reduce4(const float* __restrict__ src, float* __restrict__ dst, int n4) {
    int i = blockIdx.x * blockDim.x + threadIdx.x;
    if (i >= n4) return;
    const float4* s = (const float4*)src;
    float4 a = s[i], b = s[i + n4], c = s[i + 2 * n4], d = s[i + 3 * n4];
    float4 r = make_float4(a.x + b.x + c.x + d.x, a.y + b.y + c.y + d.y,
                           a.z + b.z + c.z + d.z, a.w + b.w + c.w + d.w);
    ((float4*)dst)[i] = r;
}

// ---------------- reduce 8 split-K xdbl buffers -> g_xdbl (fp32) + dt hi ----------------
__global__ void reduce8_xdbl(const float* __restrict__ src) {
    int i = blockIdx.x * blockDim.x + threadIdx.x;   // < NTOK*XDBL_LD/4
    const int n4 = NTOK * XDBL_LD / 4;
    if (i >= n4) return;
    const float4* s = (const float4*)src;
    float4 r = s[i];
#pragma unroll
    for (int k = 1; k < 8; k++) {
        float4 v = s[i + k * n4];
        r.x += v.x; r.y += v.y; r.z += v.z; r.w += v.w;
    }
    ((float4*)g_xdbl)[i] = r;
    int t  = i >> 5;          // row (32 float4 chunks per 128-col row)
    int cq = i & 31;
    if (cq < DTRANK / 4) {    // dt region -> fp16 hi
        int c = cq * 4;
        size_t o = (size_t)t * DTRANK + c;
        *(__half2*)&g_dth[o]     = __halves2half2(__float2half_rn(r.x), __float2half_rn(r.y));
        *(__half2*)&g_dth[o + 2] = __halves2half2(__float2half_rn(r.z), __float2half_rn(r.w));
    }
}

// ---------------- transpose body (shared) ----------------
__device__ __forceinline__ void trans_body(const float* __restrict__ W, int K, int N,
                                           __half* __restrict__ T, int bx, int by,
                                           float t[32][33])
{
    int tx = threadIdx.x, ty0 = threadIdx.y;
#pragma unroll
    for (int s = 0; s < 4; s++) {
        int ty = ty0 + s * 8;
        int col = bx * 32 + tx;          // n
        int row = by * 32 + ty;          // k
        t[ty][tx] = (col < N) ? W[(size_t)row * N + col] : 0.f;
    }
    __syncthreads();
#pragma unroll
    for (int s = 0; s < 4; s++) {
        int ty = ty0 + s * 8;
        int n = bx * 32 + ty;
        int k = by * 32 + tx;
        T[(size_t)n * K + k] = __float2half_rn(t[tx][ty]);
    }
}

// ---------------- ONE prep kernel: cvt_h(x) + all 4 weight transposes ----------------
__global__ void prep_all(const float* __restrict__ x,
                         const float* __restrict__ Win, const float* __restrict__ Wout,
                         const float* __restrict__ Wx,  const float* __restrict__ Wdt)
{
    __shared__ float t[32][33];
    int bid = blockIdx.x;
    if (bid < 2048) {
        int i = bid * 256 + threadIdx.y * 32 + threadIdx.x;   // < 524288 = NTOK*DMODEL/4
        float4 v = ((const float4*)x)[i];
        ((__half2*)g_xh)[i * 2]     = __halves2half2(__float2half_rn(v.x), __float2half_rn(v.y));
        ((__half2*)g_xh)[i * 2 + 1] = __halves2half2(__float2half_rn(v.z), __float2half_rn(v.w));
        return;
    }
    bid -= 2048;
    if (bid < 4096) { trans_body(Win, DMODEL, 2 * DINNER, g_wint, bid & 127, bid >> 7, t); return; }
    bid -= 4096;
    if (bid < 2048) { trans_body(Wout, DINNER, DMODEL, g_wot, bid & 31, bid >> 5, t); return; }
    bid -= 2048;
    if (bid < 256)  { trans_body(Wx, DINNER, DTRANK + 2 * DSTATE, g_wxt, bid & 3, bid >> 2, t); return; }
    bid -= 256;
    trans_body(Wdt, DTRANK, DINNER, g_wdtt, bid & 63, bid >> 6, t);
}

// ---------------- conv + SiLU -> fp16 uh, 4 channels/thread, fp16 inputs ----------------
__global__ void conv_silu(const float* __restrict__ ck, const float* __restrict__ cb)
{
    int idx = blockIdx.x * blockDim.x + threadIdx.x;   // < NTOK*DINNER/4
    if (idx >= NTOK * DINNER / 4) return;
    int dq = idx & (DINNER / 4 - 1);
    int bt = idx >> 9;
    int t  = bt & (SEQL - 1);
    int d  = dq * 4;

    float4 acc = *(const float4*)&cb[d];
#pragma unroll
    for (int w = 0; w < DCONV; w++) {
        int tt = t - (DCONV - 1) + w;
        if (tt >= 0) {
            float4 k = *(const float4*)&ck[w * DINNER + d];
            const __half2* up = (const __half2*)&g_uraw[(size_t)(bt - (DCONV - 1) + w) * DINNER + d];
            float2 v0 = __half22float2(up[0]);
            float2 v1 = __half22float2(up[1]);
            acc.x = fmaf(k.x, v0.x, acc.x);
            acc.y = fmaf(k.y, v0.y, acc.y);
            acc.z = fmaf(k.z, v1.x, acc.z);
            acc.w = fmaf(k.w, v1.y, acc.w);
        }
    }
    size_t o = (size_t)bt * DINNER + d;
    *(__half2*)&g_uh[o]     = __halves2half2(__float2half_rn(silu(acc.x)), __float2half_rn(silu(acc.y)));
    *(__half2*)&g_uh[o + 2] = __halves2half2(__float2half_rn(silu(acc.z)), __float2half_rn(silu(acc.w)));
}

// ---------------- chunked scan: phase 1 (chunk end-states, h0=0), smem B ----------------
__global__ __launch_bounds__(256) void scan_phase1(const float* __restrict__ A_log)
{
    __shared__ float sB[CLEN * DSTATE];    // 8 KB
    int tid = threadIdx.x;
    int ch = blockIdx.x * 16 + (tid >> 4);   // 0..4095
    int n = tid & 15;
    int c = blockIdx.y;
    int b = ch >> 11;
    int d = ch & (DINNER - 1);

    const float* xd = g_xdbl + (size_t)(b * SEQL + c * CLEN) * XDBL_LD;
    for (int i = tid; i < CLEN * DSTATE; i += 256)
        sB[i] = xd[(i >> 4) * XDBL_LD + DTRANK + (i & 15)];
    __syncthreads();

    float a = -expf(A_log[d * DSTATE + n]);
    float h = 0.f, sd = 0.f;

    const __half* dptr = g_dh + (size_t)(b * SEQL + c * CLEN) * DINNER + d;
    const __half* uptr = g_uh + (size_t)(b * SEQL + c * CLEN) * DINNER + d;

    for (int t = 0; t < CLEN; t++) {
        float delta = __half2float(dptr[(size_t)t * DINNER]);
        float uv    = __half2float(uptr[(size_t)t * DINNER]);
        float Bn    = sB[(t << 4) | n];
        h = __expf(delta * a) * h + delta * uv * Bn;
        sd += delta;
    }
    size_t idx = ((size_t)(b * DINNER + d) * DSTATE + n);
    g_hend[idx * NCHUNK + c] = h;
    if (n == 0) g_sumd[(size_t)(b * DINNER + d) * NCHUNK + c] = sd;
}

// ---------------- chunked scan: phase 2 (inline combine + y), smem B+C ----------------
__global__ __launch_bounds__(256) void scan_phase2(
    const float* __restrict__ A_log, const float* __restrict__ Dp)
{
    __shared__ float sBC[CLEN * 2 * DSTATE];   // 16 KB: [t][0..15]=B, [t][16..31]=C
    int tid = threadIdx.x;
    int ch = blockIdx.x * 16 + (tid >> 4);
    int n = tid & 15;
    int c = blockIdx.y;
    int b = ch >> 11;
    int d = ch & (DINNER - 1);

    const float* xd = g_xdbl + (size_t)(b * SEQL + c * CLEN) * XDBL_LD;
    for (int i = tid; i < CLEN * 2 * DSTATE; i += 256)
        sBC[i] = xd[(i >> 5) * XDBL_LD + DTRANK + (i & 31)];
    __syncthreads();

    float a = -expf(A_log[d * DSTATE + n]);
    float Dd = Dp[d];

    // inline combine: h0 for this chunk = fold of previous chunks
    float h = 0.f;
    {
        size_t bi = ((size_t)(b * DINNER + d) * DSTATE + n) * NCHUNK;
        size_t bs = (size_t)(b * DINNER + d) * NCHUNK;
        for (int cc = 0; cc < c; cc++)
            h = __expf(a * g_sumd[bs + cc]) * h + g_hend[bi + cc];
    }

    const __half* dptr = g_dh  + (size_t)(b * SEQL + c * CLEN) * DINNER + d;
    const __half* uptr = g_uh  + (size_t)(b * SEQL + c * CLEN) * DINNER + d;
    const __half* zptr = g_zsh + (size_t)(b * SEQL + c * CLEN) * DINNER + d;
    __half* yh = g_yh + (size_t)(b * SEQL + c * CLEN) * DINNER + d;

    for (int t = 0; t < CLEN; t++) {
        float delta = __half2float(dptr[(size_t)t * DINNER]);
        float uv    = __half2float(uptr[(size_t)t * DINNER]);
        float Bn    = sBC[(t << 5) | n];
        float Cn    = sBC[(t << 5) | 16 | n];

        h = __expf(delta * a) * h + delta * uv * Bn;

        float p = h * Cn;
        p += __shfl_xor_sync(0xffffffffu, p, 8);
        p += __shfl_xor_sync(0xffffffffu, p, 4);
        p += __shfl_xor_sync(0xffffffffu, p, 2);
        p += __shfl_xor_sync(0xffffffffu, p, 1);

        if (n == 0) {
            float v = (p + uv * Dd) * __half2float(zptr[(size_t)t * DINNER]);
            yh[(size_t)t * DINNER] = __float2half_rn(v);
        }
    }
}

// ---------------- launch ----------------
extern "C" void kernel_launch(void* const* d_in, const int* in_sizes, int n_in,
                              void* d_out, int out_size)
{
    (void)in_sizes; (void)n_in; (void)out_size;
    const float* x     = (const float*)d_in[0];
    const float* W_in  = (const float*)d_in[1];
    const float* ck    = (const float*)d_in[2];
    const float* cb    = (const float*)d_in[3];
    const float* W_x   = (const float*)d_in[4];
    const float* W_dt  = (const float*)d_in[5];
    const float* b_dt  = (const float*)d_in[6];
    const float* W_out = (const float*)d_in[7];
    const float* A_log = (const float*)d_in[8];
    const float* Dp    = (const float*)d_in[9];
    float* out = (float*)d_out;

    cudaFuncSetAttribute((const void*)mma_gemm<0>, cudaFuncAttributeMaxDynamicSharedMemorySize, MG_SMEM);
    cudaFuncSetAttribute((const void*)mma_gemm<1>, cudaFuncAttributeMaxDynamicSharedMemorySize, MG_SMEM);
    cudaFuncSetAttribute((const void*)mma_gemm<3>, cudaFuncAttributeMaxDynamicSharedMemorySize, MG_SMEM);

    float *p_osplit;
    cudaGetSymbolAddress((void**)&p_osplit, g_osplit);
    __half *xh, *uh, *yh, *dth;
    __half *wint, *wxt, *wdtt, *wot;
    cudaGetSymbolAddress((void**)&xh, g_xh);
    cudaGetSymbolAddress((void**)&uh, g_uh);
    cudaGetSymbolAddress((void**)&yh, g_yh);
    cudaGetSymbolAddress((void**)&dth, g_dth);
    cudaGetSymbolAddress((void**)&wint, g_wint);
    cudaGetSymbolAddress((void**)&wxt, g_wxt);
    cudaGetSymbolAddress((void**)&wdtt, g_wdtt);
    cudaGetSymbolAddress((void**)&wot, g_wot);

    // 1: ALL prep (cvt x + 4 weight transposes)
    prep_all<<<8576, dim3(32, 8)>>>(x, W_in, W_out, W_x, W_dt);

    // 2: xz = x @ W_in : M=2048, N=4096, K=1024; u-half -> fp16 g_uraw, z -> silu -> g_zsh
    mma_gemm<3><<<dim3(32, 16, 1), 256, MG_SMEM>>>(
        xh, DMODEL, wint, DMODEL, nullptr, 0, DMODEL, 1, nullptr, 0);

    // 3: conv + silu -> fp16 uh
    conv_silu<<<(NTOK * DINNER / 4) / 256, 256>>>(ck, cb);

    // 4: x_dbl = u @ W_x : M=2048, N=128(pad of 96), K=2048, split-K=8 -> fused reduce
    mma_gemm<0><<<dim3(1, 16, 8), 256, MG_SMEM>>>(
        uh, DINNER, wxt, DINNER, p_osplit, XDBL_LD, DINNER, 8, nullptr, NTOK * XDBL_LD);
    // 5:
    reduce8_xdbl<<<(NTOK * XDBL_LD / 4 + 255) / 256, 256>>>(p_osplit);

    // 6: delta = softplus(dt_lo @ W_dt + b_dt) : M=2048, N=2048, K=64 -> fp16 g_dh
    mma_gemm<1><<<dim3(16, 16, 1), 256, MG_SMEM>>>(
        dth, DTRANK, wdtt, DTRANK, nullptr, 0, DTRANK, 1, b_dt, 0);

    // 7,8: chunked selective scan (combine folded into phase 2)
    scan_phase1<<<dim3((BATCH * DINNER) / 16, NCHUNK), 256>>>(A_log);
    scan_phase2<<<dim3((BATCH * DINNER) / 16, NCHUNK), 256>>>(A_log, Dp);

    // 9,10: out = y @ W_out : M=2048, N=1024, K=2048, split-K=4 -> reduce
    mma_gemm<0><<<dim3(8, 16, 4), 256, MG_SMEM>>>(
        yh, DINNER, wot, DINNER, p_osplit, DMODEL, DINNER, 4, nullptr, NTOK * DMODEL);
    reduce4<<<(NTOK * DMODEL / 4 + 255) / 256, 256>>>(p_osplit, out, NTOK * DMODEL / 4);
}